// round 1
// baseline (speedup 1.0000x reference)
#include <cuda_runtime.h>

#define T_SEQ  2048
#define NB     4
#define NH     12
#define DH     64
#define DMODEL 768
#define BHN    (NB * NH)   // 48

// Scratch (allocation-free rule: __device__ globals)
__device__ float g_qkv[(size_t)3 * NB * NH * T_SEQ * DH];   // [k3][b][h][t][dh]
__device__ float g_o[(size_t)NB * T_SEQ * DMODEL];          // [b][t][h*64+dh]

// ---------------------------------------------------------------------------
// Tiled NT SGEMM: C[m,n] = sum_k A[m,k] * B[n,k], K = 768.
// BM=BN=128, BK=16, 256 threads, 8x8 per-thread tile.
// MODE 0: A = x, B = w_qkv with row map grow = dh*36 + koff; scatter into g_qkv.
//         grid.y = 18 (each block covers koff = 2*by and 2*by+1, all 64 dh each).
// MODE 1: A = g_o, B = w_out (plain), C = out, grid.y = 6.
// ---------------------------------------------------------------------------
template <int MODE>
__global__ void __launch_bounds__(256) gemm128_nt(const float* __restrict__ A,
                                                  const float* __restrict__ Bw,
                                                  float* __restrict__ C) {
    __shared__ float As[16][132];   // A^T tile: [k][m], pad 132 to tame STS conflicts
    __shared__ float Bs[16][132];   // B^T tile: [k][n]

    const int tid = threadIdx.x;
    const int tx  = tid & 15;
    const int ty  = tid >> 4;
    const int m0  = blockIdx.x * 128;
    const int by  = blockIdx.y;

    const float* Ap = (MODE == 0) ? A : g_o;

    float acc[8][8];
#pragma unroll
    for (int i = 0; i < 8; i++)
#pragma unroll
        for (int j = 0; j < 8; j++) acc[i][j] = 0.0f;

    for (int k0 = 0; k0 < DMODEL; k0 += 16) {
        // Load A tile (128x16) transposed into As
#pragma unroll
        for (int it = 0; it < 2; it++) {
            int idx = tid + it * 256;
            int row = idx >> 2, c4 = idx & 3;
            float4 v = *reinterpret_cast<const float4*>(Ap + (m0 + row) * DMODEL + k0 + c4 * 4);
            As[c4 * 4 + 0][row] = v.x;
            As[c4 * 4 + 1][row] = v.y;
            As[c4 * 4 + 2][row] = v.z;
            As[c4 * 4 + 3][row] = v.w;
        }
        // Load B tile (128x16) transposed into Bs
#pragma unroll
        for (int it = 0; it < 2; it++) {
            int idx = tid + it * 256;
            int row = idx >> 2, c4 = idx & 3;
            int grow;
            if (MODE == 0) grow = (row & 63) * 36 + by * 2 + (row >> 6);
            else           grow = by * 128 + row;
            float4 v = *reinterpret_cast<const float4*>(Bw + grow * DMODEL + k0 + c4 * 4);
            Bs[c4 * 4 + 0][row] = v.x;
            Bs[c4 * 4 + 1][row] = v.y;
            Bs[c4 * 4 + 2][row] = v.z;
            Bs[c4 * 4 + 3][row] = v.w;
        }
        __syncthreads();

#pragma unroll
        for (int kk = 0; kk < 16; kk++) {
            float4 a0 = *reinterpret_cast<const float4*>(&As[kk][ty * 4]);
            float4 a1 = *reinterpret_cast<const float4*>(&As[kk][64 + ty * 4]);
            float4 b0 = *reinterpret_cast<const float4*>(&Bs[kk][tx * 4]);
            float4 b1 = *reinterpret_cast<const float4*>(&Bs[kk][64 + tx * 4]);
            float a[8] = {a0.x, a0.y, a0.z, a0.w, a1.x, a1.y, a1.z, a1.w};
            float b[8] = {b0.x, b0.y, b0.z, b0.w, b1.x, b1.y, b1.z, b1.w};
#pragma unroll
            for (int i = 0; i < 8; i++)
#pragma unroll
                for (int j = 0; j < 8; j++) acc[i][j] += a[i] * b[j];
        }
        __syncthreads();
    }

    // Epilogue
#pragma unroll
    for (int i = 0; i < 8; i++) {
        int m = m0 + ((i < 4) ? (ty * 4 + i) : (64 + ty * 4 + i - 4));
#pragma unroll
        for (int j = 0; j < 8; j++) {
            int nl = (j < 4) ? (tx * 4 + j) : (64 + tx * 4 + j - 4);
            if (MODE == 0) {
                int koff = by * 2 + (nl >> 6);
                int dh   = nl & 63;
                int k3   = koff / 12;
                int h    = koff - k3 * 12;
                int b    = m >> 11;        // / T_SEQ
                int t    = m & 2047;       // % T_SEQ
                g_qkv[((((size_t)k3 * NB + b) * NH + h) * T_SEQ + t) * DH + dh] = acc[i][j];
            } else {
                C[(size_t)m * DMODEL + by * 128 + nl] = acc[i][j];
            }
        }
    }
}

// ---------------------------------------------------------------------------
// Flash-attention style fp32 kernel.
// grid: (T/128 = 16 q-tiles, B*H = 48). 256 threads.
// Q tile 128 rows, key tile 64; online softmax; O in registers (8 qi x 4 dh).
// energy = (q . k) * sqrt(DH) = * 8  (faithful to reference).
// ---------------------------------------------------------------------------
#define ATTN_SMEM_FLOATS (64 * 128 + 64 * 64 + 64 * 64 + 128 * 68 + 3 * 128)
#define ATTN_SMEM_BYTES  (ATTN_SMEM_FLOATS * 4)

__global__ void __launch_bounds__(256) attn_kernel() {
    extern __shared__ float sm[];
    float* QsT  = sm;                     // [dh 64][qi 128]
    float* KsT  = sm + 64 * 128;          // [dh 64][kj 64]
    float* Vs   = KsT + 64 * 64;          // [kj 64][dh 64]
    float* Ss   = Vs + 64 * 64;           // [qi 128][kj 64], ld 68
    float* mrow = Ss + 128 * 68;          // [128]
    float* lrow = mrow + 128;             // [128]
    float* arow = lrow + 128;             // [128]

    const int tid = threadIdx.x;
    const int tx  = tid & 15;
    const int ty  = tid >> 4;
    const int bh  = blockIdx.y;
    const int t0  = blockIdx.x * 128;

    const float* qp = g_qkv + (size_t)bh * (T_SEQ * DH) + (size_t)t0 * DH;
    const float* kp = g_qkv + (size_t)(BHN + bh) * (T_SEQ * DH);
    const float* vp = g_qkv + (size_t)(2 * BHN + bh) * (T_SEQ * DH);

    // Load Q tile (128 x 64) transposed
#pragma unroll
    for (int it = 0; it < 8; it++) {
        int idx = tid + it * 256;
        int row = idx >> 4, c4 = idx & 15;
        float4 v = *reinterpret_cast<const float4*>(qp + row * 64 + c4 * 4);
        QsT[(c4 * 4 + 0) * 128 + row] = v.x;
        QsT[(c4 * 4 + 1) * 128 + row] = v.y;
        QsT[(c4 * 4 + 2) * 128 + row] = v.z;
        QsT[(c4 * 4 + 3) * 128 + row] = v.w;
    }
    if (tid < 128) { mrow[tid] = -1e30f; lrow[tid] = 0.0f; }

    int qi[8];
#pragma unroll
    for (int i = 0; i < 8; i++) qi[i] = (i < 4) ? (ty * 4 + i) : (64 + ty * 4 + i - 4);

    float o[8][4];
#pragma unroll
    for (int i = 0; i < 8; i++)
#pragma unroll
        for (int j = 0; j < 4; j++) o[i][j] = 0.0f;

    __syncthreads();

    for (int kt = 0; kt < T_SEQ / 64; kt++) {
        const float* kpt = kp + kt * 64 * 64;
        const float* vpt = vp + kt * 64 * 64;
        // Load K (transposed) and V (row-major) tiles
#pragma unroll
        for (int it = 0; it < 4; it++) {
            int idx = tid + it * 256;
            int row = idx >> 4, c4 = idx & 15;
            float4 v = *reinterpret_cast<const float4*>(kpt + row * 64 + c4 * 4);
            KsT[(c4 * 4 + 0) * 64 + row] = v.x;
            KsT[(c4 * 4 + 1) * 64 + row] = v.y;
            KsT[(c4 * 4 + 2) * 64 + row] = v.z;
            KsT[(c4 * 4 + 3) * 64 + row] = v.w;
            float4 w = *reinterpret_cast<const float4*>(vpt + row * 64 + c4 * 4);
            *reinterpret_cast<float4*>(&Vs[row * 64 + c4 * 4]) = w;
        }
        __syncthreads();

        // S = Q K^T (128 x 64), 8x4 per thread
        float sacc[8][4];
#pragma unroll
        for (int i = 0; i < 8; i++)
#pragma unroll
            for (int j = 0; j < 4; j++) sacc[i][j] = 0.0f;

#pragma unroll 4
        for (int d = 0; d < 64; d++) {
            float4 a0 = *reinterpret_cast<const float4*>(&QsT[d * 128 + ty * 4]);
            float4 a1 = *reinterpret_cast<const float4*>(&QsT[d * 128 + 64 + ty * 4]);
            float4 bb = *reinterpret_cast<const float4*>(&KsT[d * 64 + tx * 4]);
            float a[8] = {a0.x, a0.y, a0.z, a0.w, a1.x, a1.y, a1.z, a1.w};
            float b[4] = {bb.x, bb.y, bb.z, bb.w};
#pragma unroll
            for (int i = 0; i < 8; i++)
#pragma unroll
                for (int j = 0; j < 4; j++) sacc[i][j] += a[i] * b[j];
        }
#pragma unroll
        for (int i = 0; i < 8; i++)
#pragma unroll
            for (int j = 0; j < 4; j++)
                Ss[qi[i] * 68 + tx * 4 + j] = sacc[i][j] * 8.0f;   // * sqrt(DH)
        __syncthreads();

        // Online softmax: 2 threads per row, 32 cols each
        {
            int row  = tid >> 1;
            int half = tid & 1;
            float* srow = Ss + row * 68 + half * 32;
            float mx = -1e30f;
#pragma unroll
            for (int c = 0; c < 32; c++) mx = fmaxf(mx, srow[c]);
            mx = fmaxf(mx, __shfl_xor_sync(0xffffffffu, mx, 1));
            float mold = mrow[row];
            float mnew = fmaxf(mold, mx);
            float ls = 0.0f;
#pragma unroll
            for (int c = 0; c < 32; c++) {
                float p = __expf(srow[c] - mnew);
                srow[c] = p;
                ls += p;
            }
            ls += __shfl_xor_sync(0xffffffffu, ls, 1);
            if (half == 0) {
                float al = __expf(mold - mnew);
                arow[row] = al;
                lrow[row] = lrow[row] * al + ls;
                mrow[row] = mnew;
            }
        }
        __syncthreads();

        // O = O * alpha + P V
#pragma unroll
        for (int i = 0; i < 8; i++) {
            float al = arow[qi[i]];
#pragma unroll
            for (int j = 0; j < 4; j++) o[i][j] *= al;
        }
#pragma unroll 2
        for (int kj = 0; kj < 64; kj++) {
            float4 v4 = *reinterpret_cast<const float4*>(&Vs[kj * 64 + tx * 4]);
            float vv[4] = {v4.x, v4.y, v4.z, v4.w};
#pragma unroll
            for (int i = 0; i < 8; i++) {
                float p = Ss[qi[i] * 68 + kj];
#pragma unroll
                for (int j = 0; j < 4; j++) o[i][j] += p * vv[j];
            }
        }
        __syncthreads();
    }

    // Writeback: g_o[b][t][h*64 + dh]
    const int b = bh / NH;
    const int h = bh - b * NH;
#pragma unroll
    for (int i = 0; i < 8; i++) {
        float linv = 1.0f / lrow[qi[i]];
        int t = t0 + qi[i];
        float* op = g_o + ((size_t)(b * T_SEQ + t)) * DMODEL + h * DH + tx * 4;
        float4 r;
        r.x = o[i][0] * linv;
        r.y = o[i][1] * linv;
        r.z = o[i][2] * linv;
        r.w = o[i][3] * linv;
        *reinterpret_cast<float4*>(op) = r;
    }
}

// ---------------------------------------------------------------------------
extern "C" void kernel_launch(void* const* d_in, const int* in_sizes, int n_in,
                              void* d_out, int out_size) {
    const float* x     = (const float*)d_in[0];   // [4, 2048, 768]
    const float* w_qkv = (const float*)d_in[1];   // [2304, 768]
    const float* w_out = (const float*)d_in[2];   // [768, 768]
    float* out = (float*)d_out;                   // [4, 2048, 768]

    cudaFuncSetAttribute(attn_kernel, cudaFuncAttributeMaxDynamicSharedMemorySize,
                         ATTN_SMEM_BYTES);

    // 1) QKV projection, fused scatter into [3,B,H,T,DH]
    gemm128_nt<0><<<dim3(64, 18), 256>>>(x, w_qkv, nullptr);
    // 2) Attention -> g_o [B,T,D]
    attn_kernel<<<dim3(16, 48), 256, ATTN_SMEM_BYTES>>>();
    // 3) Output projection
    gemm128_nt<1><<<dim3(64, 6), 256>>>(x /*unused*/, w_out, out);
}

// round 3
// speedup vs baseline: 2.5915x; 2.5915x over previous
#include <cuda_runtime.h>
#include <cstdint>

#define T_SEQ  2048
#define NB     4
#define NH     12
#define DH     64
#define DMODEL 768
#define BHN    (NB * NH)   // 48

// ---------------------------------------------------------------------------
// Device-global scratch (allocation-free rule)
// ---------------------------------------------------------------------------
__device__ uint16_t g_xh[(size_t)NB * T_SEQ * DMODEL];
__device__ uint16_t g_xl[(size_t)NB * T_SEQ * DMODEL];
__device__ uint16_t g_wqh[(size_t)3 * DMODEL * DMODEL];
__device__ uint16_t g_wql[(size_t)3 * DMODEL * DMODEL];
__device__ uint16_t g_woh[(size_t)DMODEL * DMODEL];
__device__ uint16_t g_wol[(size_t)DMODEL * DMODEL];

__device__ uint16_t g_qh[(size_t)BHN * T_SEQ * DH];
__device__ uint16_t g_ql[(size_t)BHN * T_SEQ * DH];
__device__ uint16_t g_kh[(size_t)BHN * T_SEQ * DH];
__device__ uint16_t g_kl[(size_t)BHN * T_SEQ * DH];
__device__ uint16_t g_vth[(size_t)BHN * DH * T_SEQ];   // V transposed: [bh][dh][t]
__device__ uint16_t g_vtl[(size_t)BHN * DH * T_SEQ];

__device__ uint16_t g_oh[(size_t)NB * T_SEQ * DMODEL];
__device__ uint16_t g_ol[(size_t)NB * T_SEQ * DMODEL];

// ---------------------------------------------------------------------------
// Helpers
// ---------------------------------------------------------------------------
__device__ __forceinline__ uint32_t pack2(float lo, float hi) {
    uint32_t r;
    asm("cvt.rn.bf16x2.f32 %0, %1, %2;" : "=r"(r) : "f"(hi), "f"(lo));
    return r;
}
__device__ __forceinline__ float bf16lo_f(uint32_t p) { return __uint_as_float(p << 16); }
__device__ __forceinline__ float bf16hi_f(uint32_t p) { return __uint_as_float(p & 0xffff0000u); }

__device__ __forceinline__ void split2(float x0, float x1, uint32_t& h, uint32_t& l) {
    h = pack2(x0, x1);
    l = pack2(x0 - bf16lo_f(h), x1 - bf16hi_f(h));
}

// m16n8k16 bf16 mma, fp32 accum. A row-major, B col-major.
__device__ __forceinline__ void mma_bf16(float* d, uint32_t a0, uint32_t a1, uint32_t a2,
                                         uint32_t a3, uint32_t b0, uint32_t b1) {
    asm volatile(
        "mma.sync.aligned.m16n8k16.row.col.f32.bf16.bf16.f32 "
        "{%0,%1,%2,%3}, {%4,%5,%6,%7}, {%8,%9}, {%0,%1,%2,%3};"
        : "+f"(d[0]), "+f"(d[1]), "+f"(d[2]), "+f"(d[3])
        : "r"(a0), "r"(a1), "r"(a2), "r"(a3), "r"(b0), "r"(b1));
}

// Swizzled smem byte offset within a tile of 128B rows: chunk-XOR on bits [4:6]
__device__ __forceinline__ uint32_t swz(int row, int byteoff) {
    return (uint32_t)(row * 128 + (byteoff ^ ((row & 7) << 4)));
}

// ---------------------------------------------------------------------------
// Split fp32 -> bf16 (hi, lo) for x, w_qkv, w_out
// ---------------------------------------------------------------------------
__global__ void split_all(const float* __restrict__ x, const float* __restrict__ wq,
                          const float* __restrict__ wo) {
    const int N1 = (NB * T_SEQ * DMODEL) / 4;
    const int N2 = (3 * DMODEL * DMODEL) / 4;
    const int N3 = (DMODEL * DMODEL) / 4;
    const int tot = N1 + N2 + N3;
    for (int i = blockIdx.x * blockDim.x + threadIdx.x; i < tot; i += gridDim.x * blockDim.x) {
        const float4* src;
        uint16_t *dh, *dl;
        int j;
        if (i < N1)           { src = (const float4*)x;  j = i;           dh = g_xh;  dl = g_xl; }
        else if (i < N1 + N2) { src = (const float4*)wq; j = i - N1;      dh = g_wqh; dl = g_wql; }
        else                  { src = (const float4*)wo; j = i - N1 - N2; dh = g_woh; dl = g_wol; }
        float4 v = src[j];
        uint32_t h0, l0, h1, l1;
        split2(v.x, v.y, h0, l0);
        split2(v.z, v.w, h1, l1);
        *reinterpret_cast<uint2*>(dh + 4 * (size_t)j) = uint2{h0, h1};
        *reinterpret_cast<uint2*>(dl + 4 * (size_t)j) = uint2{l0, l1};
    }
}

// ---------------------------------------------------------------------------
// mma.sync split-bf16 GEMM: C[m,n] = sum_k A[m,k]*B[n,k], K=768, tile 128x128.
// 8 warps: warp grid 4(m) x 2(n); warp tile 32x64 = 2 mtiles x 8 ntiles.
// MODE 0: A = x, B = w_qkv (row-permuted); epilogue scatters Q/K ([t][dh]) and
//         V^T ([dh][t]) as bf16 hi/lo.
// MODE 1: A = attention output (bf16 hi/lo), B = w_out; C = fp32 out.
// ---------------------------------------------------------------------------
#define GEMM_SMEM_BYTES 65536

template <int MODE>
__global__ void __launch_bounds__(256) gemm_mma(float* __restrict__ C) {
    extern __shared__ char smem[];
    const int AHo = 0, ALo = 16384, BHo = 32768, BLo = 49152;

    const int tid = threadIdx.x;
    const int lane = tid & 31;
    const int wid = tid >> 5;
    const int r = lane >> 2;
    const int c4 = (lane & 3) * 4;
    const int m0 = blockIdx.x * 128;
    const int by = blockIdx.y;
    const int wm = (wid >> 1) * 32;
    const int wn = (wid & 1) * 64;

    const uint16_t* Ah = (MODE == 0) ? g_xh : g_oh;
    const uint16_t* Al = (MODE == 0) ? g_xl : g_ol;
    const uint16_t* Bh = (MODE == 0) ? g_wqh : g_woh;
    const uint16_t* Bl = (MODE == 0) ? g_wql : g_wol;

    float acc[2][8][4];
#pragma unroll
    for (int mt = 0; mt < 2; mt++)
#pragma unroll
        for (int nt = 0; nt < 8; nt++)
#pragma unroll
            for (int q = 0; q < 4; q++) acc[mt][nt][q] = 0.0f;

    for (int c = 0; c < 12; c++) {
        const int k0 = c * 64;
        if (c) __syncthreads();
#pragma unroll
        for (int it = 0; it < 4; it++) {
            const int idx = it * 256 + tid;
            const int row = idx >> 3;
            const int ch = idx & 7;
            const uint32_t so = swz(row, ch * 16);
            // A tiles
            {
                const uint4* pa = reinterpret_cast<const uint4*>(Ah + (size_t)(m0 + row) * DMODEL + k0) + ch;
                const uint4* pb = reinterpret_cast<const uint4*>(Al + (size_t)(m0 + row) * DMODEL + k0) + ch;
                *reinterpret_cast<uint4*>(smem + AHo + so) = *pa;
                *reinterpret_cast<uint4*>(smem + ALo + so) = *pb;
            }
            // B tiles (row permutation for MODE 0)
            {
                int grow = (MODE == 0) ? ((row & 63) * 36 + by * 2 + (row >> 6)) : (by * 128 + row);
                const uint4* pa = reinterpret_cast<const uint4*>(Bh + (size_t)grow * DMODEL + k0) + ch;
                const uint4* pb = reinterpret_cast<const uint4*>(Bl + (size_t)grow * DMODEL + k0) + ch;
                *reinterpret_cast<uint4*>(smem + BHo + so) = *pa;
                *reinterpret_cast<uint4*>(smem + BLo + so) = *pb;
            }
        }
        __syncthreads();

#pragma unroll
        for (int kt = 0; kt < 4; kt++) {
            uint32_t aH[2][4], aL[2][4];
#pragma unroll
            for (int mt = 0; mt < 2; mt++) {
                const int row = wm + mt * 16 + r;
                const uint32_t o0 = swz(row, kt * 32 + c4);
                const uint32_t o2 = swz(row, kt * 32 + c4 + 16);
                aH[mt][0] = *reinterpret_cast<const uint32_t*>(smem + AHo + o0);
                aH[mt][1] = *reinterpret_cast<const uint32_t*>(smem + AHo + o0 + 1024);
                aH[mt][2] = *reinterpret_cast<const uint32_t*>(smem + AHo + o2);
                aH[mt][3] = *reinterpret_cast<const uint32_t*>(smem + AHo + o2 + 1024);
                aL[mt][0] = *reinterpret_cast<const uint32_t*>(smem + ALo + o0);
                aL[mt][1] = *reinterpret_cast<const uint32_t*>(smem + ALo + o0 + 1024);
                aL[mt][2] = *reinterpret_cast<const uint32_t*>(smem + ALo + o2);
                aL[mt][3] = *reinterpret_cast<const uint32_t*>(smem + ALo + o2 + 1024);
            }
#pragma unroll
            for (int nt = 0; nt < 8; nt++) {
                const int rowb = wn + nt * 8 + r;
                const uint32_t ob0 = swz(rowb, kt * 32 + c4);
                const uint32_t ob1 = swz(rowb, kt * 32 + c4 + 16);
                const uint32_t bh0 = *reinterpret_cast<const uint32_t*>(smem + BHo + ob0);
                const uint32_t bh1 = *reinterpret_cast<const uint32_t*>(smem + BHo + ob1);
                const uint32_t bl0 = *reinterpret_cast<const uint32_t*>(smem + BLo + ob0);
                const uint32_t bl1 = *reinterpret_cast<const uint32_t*>(smem + BLo + ob1);
#pragma unroll
                for (int mt = 0; mt < 2; mt++) {
                    mma_bf16(acc[mt][nt], aH[mt][0], aH[mt][1], aH[mt][2], aH[mt][3], bh0, bh1);
                    mma_bf16(acc[mt][nt], aH[mt][0], aH[mt][1], aH[mt][2], aH[mt][3], bl0, bl1);
                    mma_bf16(acc[mt][nt], aL[mt][0], aL[mt][1], aL[mt][2], aL[mt][3], bh0, bh1);
                }
            }
        }
    }

    // Epilogue
#pragma unroll
    for (int mt = 0; mt < 2; mt++) {
        const int mrow = m0 + wm + mt * 16 + r;
#pragma unroll
        for (int nt = 0; nt < 8; nt++) {
            const int nl = wn + nt * 8 + 2 * (lane & 3);
            const float d0 = acc[mt][nt][0], d1 = acc[mt][nt][1];
            const float d2 = acc[mt][nt][2], d3 = acc[mt][nt][3];
            if (MODE == 0) {
                const int koff = by * 2 + (nl >> 6);
                const int dh = nl & 63;
                const int k3 = koff / 12;
                const int h = koff - 12 * k3;
                const int b = mrow >> 11;
                const int t = mrow & 2047;
                const int bhI = b * NH + h;
                uint32_t h0, l0, h1, l1;
                split2(d0, d1, h0, l0);
                split2(d2, d3, h1, l1);
                if (k3 == 0) {
                    size_t p0 = ((size_t)bhI * T_SEQ + t) * DH + dh;
                    size_t p1 = ((size_t)bhI * T_SEQ + t + 8) * DH + dh;
                    *reinterpret_cast<uint32_t*>(g_qh + p0) = h0;
                    *reinterpret_cast<uint32_t*>(g_ql + p0) = l0;
                    *reinterpret_cast<uint32_t*>(g_qh + p1) = h1;
                    *reinterpret_cast<uint32_t*>(g_ql + p1) = l1;
                } else if (k3 == 1) {
                    size_t p0 = ((size_t)bhI * T_SEQ + t) * DH + dh;
                    size_t p1 = ((size_t)bhI * T_SEQ + t + 8) * DH + dh;
                    *reinterpret_cast<uint32_t*>(g_kh + p0) = h0;
                    *reinterpret_cast<uint32_t*>(g_kl + p0) = l0;
                    *reinterpret_cast<uint32_t*>(g_kh + p1) = h1;
                    *reinterpret_cast<uint32_t*>(g_kl + p1) = l1;
                } else {
                    size_t q0 = ((size_t)bhI * DH + dh) * T_SEQ + t;
                    size_t q1 = ((size_t)bhI * DH + dh + 1) * T_SEQ + t;
                    g_vth[q0] = (uint16_t)h0;      g_vth[q1] = (uint16_t)(h0 >> 16);
                    g_vtl[q0] = (uint16_t)l0;      g_vtl[q1] = (uint16_t)(l0 >> 16);
                    g_vth[q0 + 8] = (uint16_t)h1;  g_vth[q1 + 8] = (uint16_t)(h1 >> 16);
                    g_vtl[q0 + 8] = (uint16_t)l1;  g_vtl[q1 + 8] = (uint16_t)(l1 >> 16);
                }
            } else {
                float2 p0{d0, d1}, p1{d2, d3};
                *reinterpret_cast<float2*>(C + (size_t)mrow * DMODEL + by * 128 + nl) = p0;
                *reinterpret_cast<float2*>(C + (size_t)(mrow + 8) * DMODEL + by * 128 + nl) = p1;
            }
        }
    }
}

// ---------------------------------------------------------------------------
// Flash attention via mma.sync bf16 splits; softmax fully in registers.
// grid (16 qtiles, 48 bh), 256 threads = 8 warps, each warp owns 16 q-rows.
// ---------------------------------------------------------------------------
#define ATTN_SMEM_BYTES 65536

__global__ void __launch_bounds__(256) attn_mma() {
    extern __shared__ char smem[];
    const int QHo = 0, QLo = 16384, KHo = 32768, KLo = 40960, VHo = 49152, VLo = 57344;

    const int tid = threadIdx.x;
    const int lane = tid & 31;
    const int wid = tid >> 5;
    const int r = lane >> 2;
    const int c4 = (lane & 3) * 4;
    const int bh = blockIdx.y;
    const int t0 = blockIdx.x * 128;
    const int wrow = wid * 16;

    // Stage Q hi/lo tiles [128][64]
    const uint16_t* qh = g_qh + ((size_t)bh * T_SEQ + t0) * DH;
    const uint16_t* ql = g_ql + ((size_t)bh * T_SEQ + t0) * DH;
#pragma unroll
    for (int it = 0; it < 4; it++) {
        const int idx = it * 256 + tid;
        const int row = idx >> 3;
        const int ch = idx & 7;
        const uint32_t so = swz(row, ch * 16);
        *reinterpret_cast<uint4*>(smem + QHo + so) =
            *(reinterpret_cast<const uint4*>(qh + (size_t)row * DH) + ch);
        *reinterpret_cast<uint4*>(smem + QLo + so) =
            *(reinterpret_cast<const uint4*>(ql + (size_t)row * DH) + ch);
    }

    float m0s = -1e30f, m1s = -1e30f, l0s = 0.0f, l1s = 0.0f;
    float o[8][4];
#pragma unroll
    for (int nt = 0; nt < 8; nt++)
#pragma unroll
        for (int q = 0; q < 4; q++) o[nt][q] = 0.0f;

    const uint16_t* kh = g_kh + (size_t)bh * T_SEQ * DH;
    const uint16_t* kl = g_kl + (size_t)bh * T_SEQ * DH;
    const uint16_t* vh = g_vth + (size_t)bh * DH * T_SEQ;
    const uint16_t* vl = g_vtl + (size_t)bh * DH * T_SEQ;

    __syncthreads();

    for (int kt64 = 0; kt64 < T_SEQ / 64; kt64++) {
        if (kt64) __syncthreads();
        // Load K hi/lo [64 keys][64 dh] and V^T hi/lo [64 dh][64 keys]
#pragma unroll
        for (int it = 0; it < 2; it++) {
            const int idx = it * 256 + tid;
            const int row = idx >> 3;
            const int ch = idx & 7;
            const uint32_t so = swz(row, ch * 16);
            *reinterpret_cast<uint4*>(smem + KHo + so) =
                *(reinterpret_cast<const uint4*>(kh + (size_t)(kt64 * 64 + row) * DH) + ch);
            *reinterpret_cast<uint4*>(smem + KLo + so) =
                *(reinterpret_cast<const uint4*>(kl + (size_t)(kt64 * 64 + row) * DH) + ch);
            *reinterpret_cast<uint4*>(smem + VHo + so) =
                *(reinterpret_cast<const uint4*>(vh + (size_t)row * T_SEQ + kt64 * 64) + ch);
            *reinterpret_cast<uint4*>(smem + VLo + so) =
                *(reinterpret_cast<const uint4*>(vl + (size_t)row * T_SEQ + kt64 * 64) + ch);
        }
        __syncthreads();

        // ---- S = Q K^T (16 x 64 per warp) ----
        float s[8][4];
#pragma unroll
        for (int nt = 0; nt < 8; nt++)
#pragma unroll
            for (int q = 0; q < 4; q++) s[nt][q] = 0.0f;

#pragma unroll
        for (int kt = 0; kt < 4; kt++) {
            const int row = wrow + r;
            const uint32_t o0 = swz(row, kt * 32 + c4);
            const uint32_t o2 = swz(row, kt * 32 + c4 + 16);
            uint32_t qa[4], qb[4];
            qa[0] = *reinterpret_cast<const uint32_t*>(smem + QHo + o0);
            qa[1] = *reinterpret_cast<const uint32_t*>(smem + QHo + o0 + 1024);
            qa[2] = *reinterpret_cast<const uint32_t*>(smem + QHo + o2);
            qa[3] = *reinterpret_cast<const uint32_t*>(smem + QHo + o2 + 1024);
            qb[0] = *reinterpret_cast<const uint32_t*>(smem + QLo + o0);
            qb[1] = *reinterpret_cast<const uint32_t*>(smem + QLo + o0 + 1024);
            qb[2] = *reinterpret_cast<const uint32_t*>(smem + QLo + o2);
            qb[3] = *reinterpret_cast<const uint32_t*>(smem + QLo + o2 + 1024);
#pragma unroll
            for (int nt = 0; nt < 8; nt++) {
                const int rowb = nt * 8 + r;
                const uint32_t ob0 = swz(rowb, kt * 32 + c4);
                const uint32_t ob1 = swz(rowb, kt * 32 + c4 + 16);
                const uint32_t kh0 = *reinterpret_cast<const uint32_t*>(smem + KHo + ob0);
                const uint32_t kh1 = *reinterpret_cast<const uint32_t*>(smem + KHo + ob1);
                const uint32_t kl0 = *reinterpret_cast<const uint32_t*>(smem + KLo + ob0);
                const uint32_t kl1 = *reinterpret_cast<const uint32_t*>(smem + KLo + ob1);
                mma_bf16(s[nt], qa[0], qa[1], qa[2], qa[3], kh0, kh1);
                mma_bf16(s[nt], qa[0], qa[1], qa[2], qa[3], kl0, kl1);
                mma_bf16(s[nt], qb[0], qb[1], qb[2], qb[3], kh0, kh1);
            }
        }

        // ---- online softmax (registers; quad shfl reduce) ----
        float mx0 = -1e30f, mx1 = -1e30f;
#pragma unroll
        for (int nt = 0; nt < 8; nt++) {
            mx0 = fmaxf(mx0, fmaxf(s[nt][0], s[nt][1]));
            mx1 = fmaxf(mx1, fmaxf(s[nt][2], s[nt][3]));
        }
        mx0 = fmaxf(mx0, __shfl_xor_sync(0xffffffffu, mx0, 1));
        mx0 = fmaxf(mx0, __shfl_xor_sync(0xffffffffu, mx0, 2));
        mx1 = fmaxf(mx1, __shfl_xor_sync(0xffffffffu, mx1, 1));
        mx1 = fmaxf(mx1, __shfl_xor_sync(0xffffffffu, mx1, 2));

        const float mn0 = fmaxf(m0s, 8.0f * mx0);   // *sqrt(DH) scale
        const float mn1 = fmaxf(m1s, 8.0f * mx1);
        const float al0 = __expf(m0s - mn0);
        const float al1 = __expf(m1s - mn1);
        m0s = mn0; m1s = mn1;

        float rs0 = 0.0f, rs1 = 0.0f;
#pragma unroll
        for (int nt = 0; nt < 8; nt++) {
            float p0 = __expf(fmaf(8.0f, s[nt][0], -mn0));
            float p1 = __expf(fmaf(8.0f, s[nt][1], -mn0));
            float p2 = __expf(fmaf(8.0f, s[nt][2], -mn1));
            float p3 = __expf(fmaf(8.0f, s[nt][3], -mn1));
            s[nt][0] = p0; s[nt][1] = p1; s[nt][2] = p2; s[nt][3] = p3;
            rs0 += p0 + p1;
            rs1 += p2 + p3;
        }
        rs0 += __shfl_xor_sync(0xffffffffu, rs0, 1);
        rs0 += __shfl_xor_sync(0xffffffffu, rs0, 2);
        rs1 += __shfl_xor_sync(0xffffffffu, rs1, 1);
        rs1 += __shfl_xor_sync(0xffffffffu, rs1, 2);
        l0s = l0s * al0 + rs0;
        l1s = l1s * al1 + rs1;

#pragma unroll
        for (int nt = 0; nt < 8; nt++) {
            o[nt][0] *= al0; o[nt][1] *= al0;
            o[nt][2] *= al1; o[nt][3] *= al1;
        }

        // ---- O += P V : P fragments packed from registers ----
#pragma unroll
        for (int kt = 0; kt < 4; kt++) {
            uint32_t ph[4], pl[4];
            {
                float x0 = s[2 * kt][0], x1 = s[2 * kt][1];
                float x2 = s[2 * kt][2], x3 = s[2 * kt][3];
                float y0 = s[2 * kt + 1][0], y1 = s[2 * kt + 1][1];
                float y2 = s[2 * kt + 1][2], y3 = s[2 * kt + 1][3];
                split2(x0, x1, ph[0], pl[0]);
                split2(x2, x3, ph[1], pl[1]);
                split2(y0, y1, ph[2], pl[2]);
                split2(y2, y3, ph[3], pl[3]);
            }
#pragma unroll
            for (int nt = 0; nt < 8; nt++) {
                const int rowv = nt * 8 + r;
                const uint32_t ov0 = swz(rowv, kt * 32 + c4);
                const uint32_t ov1 = swz(rowv, kt * 32 + c4 + 16);
                const uint32_t vh0 = *reinterpret_cast<const uint32_t*>(smem + VHo + ov0);
                const uint32_t vh1 = *reinterpret_cast<const uint32_t*>(smem + VHo + ov1);
                const uint32_t vl0 = *reinterpret_cast<const uint32_t*>(smem + VLo + ov0);
                const uint32_t vl1 = *reinterpret_cast<const uint32_t*>(smem + VLo + ov1);
                mma_bf16(o[nt], ph[0], ph[1], ph[2], ph[3], vh0, vh1);
                mma_bf16(o[nt], ph[0], ph[1], ph[2], ph[3], vl0, vl1);
                mma_bf16(o[nt], pl[0], pl[1], pl[2], pl[3], vh0, vh1);
            }
        }
    }

    // Writeback -> g_oh/g_ol at [b][t][h*64+dh]
    const float li0 = 1.0f / l0s;
    const float li1 = 1.0f / l1s;
    const int b = bh / NH;
    const int h = bh - b * NH;
    const int t_r = t0 + wrow + r;
#pragma unroll
    for (int nt = 0; nt < 8; nt++) {
        const int col = h * DH + nt * 8 + 2 * (lane & 3);
        uint32_t h0, l0, h1, l1;
        split2(o[nt][0] * li0, o[nt][1] * li0, h0, l0);
        split2(o[nt][2] * li1, o[nt][3] * li1, h1, l1);
        size_t p0 = ((size_t)b * T_SEQ + t_r) * DMODEL + col;
        size_t p1 = ((size_t)b * T_SEQ + t_r + 8) * DMODEL + col;
        *reinterpret_cast<uint32_t*>(g_oh + p0) = h0;
        *reinterpret_cast<uint32_t*>(g_ol + p0) = l0;
        *reinterpret_cast<uint32_t*>(g_oh + p1) = h1;
        *reinterpret_cast<uint32_t*>(g_ol + p1) = l1;
    }
}

// ---------------------------------------------------------------------------
extern "C" void kernel_launch(void* const* d_in, const int* in_sizes, int n_in,
                              void* d_out, int out_size) {
    const float* x     = (const float*)d_in[0];   // [4, 2048, 768]
    const float* w_qkv = (const float*)d_in[1];   // [2304, 768]
    const float* w_out = (const float*)d_in[2];   // [768, 768]
    float* out = (float*)d_out;                   // [4, 2048, 768]

    cudaFuncSetAttribute(gemm_mma<0>, cudaFuncAttributeMaxDynamicSharedMemorySize, GEMM_SMEM_BYTES);
    cudaFuncSetAttribute(gemm_mma<1>, cudaFuncAttributeMaxDynamicSharedMemorySize, GEMM_SMEM_BYTES);
    cudaFuncSetAttribute(attn_mma,    cudaFuncAttributeMaxDynamicSharedMemorySize, ATTN_SMEM_BYTES);

    split_all<<<512, 256>>>(x, w_qkv, w_out);
    gemm_mma<0><<<dim3(64, 18), 256, GEMM_SMEM_BYTES>>>(nullptr);
    attn_mma<<<dim3(16, 48), 256, ATTN_SMEM_BYTES>>>();
    gemm_mma<1><<<dim3(64, 6), 256, GEMM_SMEM_BYTES>>>(out);
}

// round 4
// speedup vs baseline: 2.9648x; 1.1440x over previous
#include <cuda_runtime.h>
#include <cstdint>

#define T_SEQ  2048
#define NB     4
#define NH     12
#define DH     64
#define DMODEL 768
#define BHN    (NB * NH)   // 48

// ---------------------------------------------------------------------------
// Device-global scratch (allocation-free rule)
// ---------------------------------------------------------------------------
__device__ uint16_t g_xh[(size_t)NB * T_SEQ * DMODEL];
__device__ uint16_t g_xl[(size_t)NB * T_SEQ * DMODEL];
__device__ uint16_t g_wqh[(size_t)3 * DMODEL * DMODEL];
__device__ uint16_t g_wql[(size_t)3 * DMODEL * DMODEL];
__device__ uint16_t g_woh[(size_t)DMODEL * DMODEL];
__device__ uint16_t g_wol[(size_t)DMODEL * DMODEL];

__device__ uint16_t g_qh[(size_t)BHN * T_SEQ * DH];
__device__ uint16_t g_ql[(size_t)BHN * T_SEQ * DH];
__device__ uint16_t g_kh[(size_t)BHN * T_SEQ * DH];
__device__ uint16_t g_kl[(size_t)BHN * T_SEQ * DH];
__device__ uint16_t g_vth[(size_t)BHN * DH * T_SEQ];   // V transposed: [bh][dh][t]
__device__ uint16_t g_vtl[(size_t)BHN * DH * T_SEQ];

__device__ uint16_t g_oh[(size_t)NB * T_SEQ * DMODEL];
__device__ uint16_t g_ol[(size_t)NB * T_SEQ * DMODEL];

// ---------------------------------------------------------------------------
// Helpers
// ---------------------------------------------------------------------------
__device__ __forceinline__ uint32_t smem_u32(const void* p) {
    uint32_t a;
    asm("{ .reg .u64 t; cvta.to.shared.u64 t, %1; cvt.u32.u64 %0, t; }"
        : "=r"(a) : "l"(p));
    return a;
}

__device__ __forceinline__ uint32_t pack2(float lo, float hi) {
    uint32_t r;
    asm("cvt.rn.bf16x2.f32 %0, %1, %2;" : "=r"(r) : "f"(hi), "f"(lo));
    return r;
}
__device__ __forceinline__ float bf16lo_f(uint32_t p) { return __uint_as_float(p << 16); }
__device__ __forceinline__ float bf16hi_f(uint32_t p) { return __uint_as_float(p & 0xffff0000u); }

__device__ __forceinline__ void split2(float x0, float x1, uint32_t& h, uint32_t& l) {
    h = pack2(x0, x1);
    l = pack2(x0 - bf16lo_f(h), x1 - bf16hi_f(h));
}

// m16n8k16 bf16 mma, fp32 accum. A row-major, B col-major.
__device__ __forceinline__ void mma_bf16(float* d, uint32_t a0, uint32_t a1, uint32_t a2,
                                         uint32_t a3, uint32_t b0, uint32_t b1) {
    asm volatile(
        "mma.sync.aligned.m16n8k16.row.col.f32.bf16.bf16.f32 "
        "{%0,%1,%2,%3}, {%4,%5,%6,%7}, {%8,%9}, {%0,%1,%2,%3};"
        : "+f"(d[0]), "+f"(d[1]), "+f"(d[2]), "+f"(d[3])
        : "r"(a0), "r"(a1), "r"(a2), "r"(a3), "r"(b0), "r"(b1));
}

// Swizzled smem byte offset within a tile of 128B rows: chunk-XOR on bits [4:6]
__device__ __forceinline__ uint32_t swz(int row, int byteoff) {
    return (uint32_t)(row * 128 + (byteoff ^ ((row & 7) << 4)));
}

// cp.async helpers (16B, L2-only path)
#define CP_ASYNC16(dst_u32, src_ptr) \
    asm volatile("cp.async.cg.shared.global [%0], [%1], 16;" \
                 :: "r"(dst_u32), "l"(src_ptr) : "memory")
#define CP_COMMIT() asm volatile("cp.async.commit_group;" ::: "memory")
#define CP_WAIT1()  asm volatile("cp.async.wait_group 1;" ::: "memory")
#define CP_WAIT0()  asm volatile("cp.async.wait_group 0;" ::: "memory")

// ---------------------------------------------------------------------------
// Split fp32 -> bf16 (hi, lo) for x, w_qkv, w_out
// ---------------------------------------------------------------------------
__global__ void split_all(const float* __restrict__ x, const float* __restrict__ wq,
                          const float* __restrict__ wo) {
    const int N1 = (NB * T_SEQ * DMODEL) / 4;
    const int N2 = (3 * DMODEL * DMODEL) / 4;
    const int N3 = (DMODEL * DMODEL) / 4;
    const int tot = N1 + N2 + N3;
    for (int i = blockIdx.x * blockDim.x + threadIdx.x; i < tot; i += gridDim.x * blockDim.x) {
        const float4* src;
        uint16_t *dh, *dl;
        int j;
        if (i < N1)           { src = (const float4*)x;  j = i;           dh = g_xh;  dl = g_xl; }
        else if (i < N1 + N2) { src = (const float4*)wq; j = i - N1;      dh = g_wqh; dl = g_wql; }
        else                  { src = (const float4*)wo; j = i - N1 - N2; dh = g_woh; dl = g_wol; }
        float4 v = src[j];
        uint32_t h0, l0, h1, l1;
        split2(v.x, v.y, h0, l0);
        split2(v.z, v.w, h1, l1);
        *reinterpret_cast<uint2*>(dh + 4 * (size_t)j) = uint2{h0, h1};
        *reinterpret_cast<uint2*>(dl + 4 * (size_t)j) = uint2{l0, l1};
    }
}

// ---------------------------------------------------------------------------
// mma.sync split-bf16 GEMM with cp.async double-buffering.
// C[m,n] = sum_k A[m,k]*B[n,k], K=768, CTA tile 128x128, warp tile 32x64.
// ---------------------------------------------------------------------------
#define GEMM_BUF     65536
#define GEMM_SMEM_BYTES (2 * GEMM_BUF)

template <int MODE>
__global__ void __launch_bounds__(256) gemm_mma(float* __restrict__ C) {
    extern __shared__ char smem[];
    const uint32_t sb = smem_u32(smem);
    const int AHo = 0, ALo = 16384, BHo = 32768, BLo = 49152;

    const int tid = threadIdx.x;
    const int lane = tid & 31;
    const int wid = tid >> 5;
    const int r = lane >> 2;
    const int c4 = (lane & 3) * 4;
    const int m0 = blockIdx.x * 128;
    const int by = blockIdx.y;
    const int wm = (wid >> 1) * 32;
    const int wn = (wid & 1) * 64;

    const uint16_t* Ah = (MODE == 0) ? g_xh : g_oh;
    const uint16_t* Al = (MODE == 0) ? g_xl : g_ol;
    const uint16_t* Bh = (MODE == 0) ? g_wqh : g_woh;
    const uint16_t* Bl = (MODE == 0) ? g_wql : g_wol;

    // issue one K-chunk stage into buffer `buf`
    auto issue_stage = [&](int c, int buf) {
        const int k0 = c * 64;
        const uint32_t base = sb + buf * GEMM_BUF;
#pragma unroll
        for (int it = 0; it < 4; it++) {
            const int idx = it * 256 + tid;
            const int row = idx >> 3;
            const int ch = idx & 7;
            const uint32_t so = swz(row, ch * 16);
            CP_ASYNC16(base + AHo + so, Ah + (size_t)(m0 + row) * DMODEL + k0 + ch * 8);
            CP_ASYNC16(base + ALo + so, Al + (size_t)(m0 + row) * DMODEL + k0 + ch * 8);
            const int grow = (MODE == 0) ? ((row & 63) * 36 + by * 2 + (row >> 6))
                                         : (by * 128 + row);
            CP_ASYNC16(base + BHo + so, Bh + (size_t)grow * DMODEL + k0 + ch * 8);
            CP_ASYNC16(base + BLo + so, Bl + (size_t)grow * DMODEL + k0 + ch * 8);
        }
        CP_COMMIT();
    };

    float acc[2][8][4];
#pragma unroll
    for (int mt = 0; mt < 2; mt++)
#pragma unroll
        for (int nt = 0; nt < 8; nt++)
#pragma unroll
            for (int q = 0; q < 4; q++) acc[mt][nt][q] = 0.0f;

    issue_stage(0, 0);

    for (int c = 0; c < 12; c++) {
        if (c + 1 < 12) { issue_stage(c + 1, (c + 1) & 1); CP_WAIT1(); }
        else            { CP_WAIT0(); }
        __syncthreads();
        const char* bp = smem + (c & 1) * GEMM_BUF;

#pragma unroll
        for (int kt = 0; kt < 4; kt++) {
            uint32_t aH[2][4], aL[2][4];
#pragma unroll
            for (int mt = 0; mt < 2; mt++) {
                const int row = wm + mt * 16 + r;
                const uint32_t o0 = swz(row, kt * 32 + c4);
                const uint32_t o2 = swz(row, kt * 32 + c4 + 16);
                aH[mt][0] = *reinterpret_cast<const uint32_t*>(bp + AHo + o0);
                aH[mt][1] = *reinterpret_cast<const uint32_t*>(bp + AHo + o0 + 1024);
                aH[mt][2] = *reinterpret_cast<const uint32_t*>(bp + AHo + o2);
                aH[mt][3] = *reinterpret_cast<const uint32_t*>(bp + AHo + o2 + 1024);
                aL[mt][0] = *reinterpret_cast<const uint32_t*>(bp + ALo + o0);
                aL[mt][1] = *reinterpret_cast<const uint32_t*>(bp + ALo + o0 + 1024);
                aL[mt][2] = *reinterpret_cast<const uint32_t*>(bp + ALo + o2);
                aL[mt][3] = *reinterpret_cast<const uint32_t*>(bp + ALo + o2 + 1024);
            }
#pragma unroll
            for (int nt = 0; nt < 8; nt++) {
                const int rowb = wn + nt * 8 + r;
                const uint32_t ob0 = swz(rowb, kt * 32 + c4);
                const uint32_t ob1 = swz(rowb, kt * 32 + c4 + 16);
                const uint32_t bh0 = *reinterpret_cast<const uint32_t*>(bp + BHo + ob0);
                const uint32_t bh1 = *reinterpret_cast<const uint32_t*>(bp + BHo + ob1);
                const uint32_t bl0 = *reinterpret_cast<const uint32_t*>(bp + BLo + ob0);
                const uint32_t bl1 = *reinterpret_cast<const uint32_t*>(bp + BLo + ob1);
#pragma unroll
                for (int mt = 0; mt < 2; mt++) {
                    mma_bf16(acc[mt][nt], aH[mt][0], aH[mt][1], aH[mt][2], aH[mt][3], bh0, bh1);
                    mma_bf16(acc[mt][nt], aH[mt][0], aH[mt][1], aH[mt][2], aH[mt][3], bl0, bl1);
                    mma_bf16(acc[mt][nt], aL[mt][0], aL[mt][1], aL[mt][2], aL[mt][3], bh0, bh1);
                }
            }
        }
        __syncthreads();
    }

    // Epilogue
#pragma unroll
    for (int mt = 0; mt < 2; mt++) {
        const int mrow = m0 + wm + mt * 16 + r;
#pragma unroll
        for (int nt = 0; nt < 8; nt++) {
            const int nl = wn + nt * 8 + 2 * (lane & 3);
            const float d0 = acc[mt][nt][0], d1 = acc[mt][nt][1];
            const float d2 = acc[mt][nt][2], d3 = acc[mt][nt][3];
            if (MODE == 0) {
                const int koff = by * 2 + (nl >> 6);
                const int dh = nl & 63;
                const int k3 = koff / 12;
                const int h = koff - 12 * k3;
                const int b = mrow >> 11;
                const int t = mrow & 2047;
                const int bhI = b * NH + h;
                uint32_t h0, l0, h1, l1;
                split2(d0, d1, h0, l0);
                split2(d2, d3, h1, l1);
                if (k3 == 0) {
                    size_t p0 = ((size_t)bhI * T_SEQ + t) * DH + dh;
                    size_t p1 = ((size_t)bhI * T_SEQ + t + 8) * DH + dh;
                    *reinterpret_cast<uint32_t*>(g_qh + p0) = h0;
                    *reinterpret_cast<uint32_t*>(g_ql + p0) = l0;
                    *reinterpret_cast<uint32_t*>(g_qh + p1) = h1;
                    *reinterpret_cast<uint32_t*>(g_ql + p1) = l1;
                } else if (k3 == 1) {
                    size_t p0 = ((size_t)bhI * T_SEQ + t) * DH + dh;
                    size_t p1 = ((size_t)bhI * T_SEQ + t + 8) * DH + dh;
                    *reinterpret_cast<uint32_t*>(g_kh + p0) = h0;
                    *reinterpret_cast<uint32_t*>(g_kl + p0) = l0;
                    *reinterpret_cast<uint32_t*>(g_kh + p1) = h1;
                    *reinterpret_cast<uint32_t*>(g_kl + p1) = l1;
                } else {
                    size_t q0 = ((size_t)bhI * DH + dh) * T_SEQ + t;
                    size_t q1 = ((size_t)bhI * DH + dh + 1) * T_SEQ + t;
                    g_vth[q0] = (uint16_t)h0;      g_vth[q1] = (uint16_t)(h0 >> 16);
                    g_vtl[q0] = (uint16_t)l0;      g_vtl[q1] = (uint16_t)(l0 >> 16);
                    g_vth[q0 + 8] = (uint16_t)h1;  g_vth[q1 + 8] = (uint16_t)(h1 >> 16);
                    g_vtl[q0 + 8] = (uint16_t)l1;  g_vtl[q1 + 8] = (uint16_t)(l1 >> 16);
                }
            } else {
                float2 p0{d0, d1}, p1{d2, d3};
                *reinterpret_cast<float2*>(C + (size_t)mrow * DMODEL + by * 128 + nl) = p0;
                *reinterpret_cast<float2*>(C + (size_t)(mrow + 8) * DMODEL + by * 128 + nl) = p1;
            }
        }
    }
}

// ---------------------------------------------------------------------------
// Flash attention via mma.sync bf16 splits; softmax in registers;
// cp.async double-buffered K/V tiles.
// ---------------------------------------------------------------------------
#define ATTN_KV_BUF   32768
#define ATTN_SMEM_BYTES (32768 + 2 * ATTN_KV_BUF)   // Q(32K) + 2 KV stages

__global__ void __launch_bounds__(256) attn_mma() {
    extern __shared__ char smem[];
    const uint32_t sb = smem_u32(smem);
    const int QHo = 0, QLo = 16384;
    const int KHo = 0, KLo = 8192, VHo = 16384, VLo = 24576;   // within KV stage

    const int tid = threadIdx.x;
    const int lane = tid & 31;
    const int wid = tid >> 5;
    const int r = lane >> 2;
    const int c4 = (lane & 3) * 4;
    const int bh = blockIdx.y;
    const int t0 = blockIdx.x * 128;
    const int wrow = wid * 16;

    const uint16_t* kh = g_kh + (size_t)bh * T_SEQ * DH;
    const uint16_t* kl = g_kl + (size_t)bh * T_SEQ * DH;
    const uint16_t* vh = g_vth + (size_t)bh * DH * T_SEQ;
    const uint16_t* vl = g_vtl + (size_t)bh * DH * T_SEQ;

    auto issue_kv = [&](int kt, int buf) {
        const uint32_t base = sb + 32768 + buf * ATTN_KV_BUF;
#pragma unroll
        for (int it = 0; it < 2; it++) {
            const int idx = it * 256 + tid;
            const int row = idx >> 3;
            const int ch = idx & 7;
            const uint32_t so = swz(row, ch * 16);
            CP_ASYNC16(base + KHo + so, kh + (size_t)(kt * 64 + row) * DH + ch * 8);
            CP_ASYNC16(base + KLo + so, kl + (size_t)(kt * 64 + row) * DH + ch * 8);
            CP_ASYNC16(base + VHo + so, vh + (size_t)row * T_SEQ + kt * 64 + ch * 8);
            CP_ASYNC16(base + VLo + so, vl + (size_t)row * T_SEQ + kt * 64 + ch * 8);
        }
        CP_COMMIT();
    };

    issue_kv(0, 0);

    // Stage Q hi/lo tiles [128][64] (regular stores)
    const uint16_t* qh = g_qh + ((size_t)bh * T_SEQ + t0) * DH;
    const uint16_t* ql = g_ql + ((size_t)bh * T_SEQ + t0) * DH;
#pragma unroll
    for (int it = 0; it < 4; it++) {
        const int idx = it * 256 + tid;
        const int row = idx >> 3;
        const int ch = idx & 7;
        const uint32_t so = swz(row, ch * 16);
        *reinterpret_cast<uint4*>(smem + QHo + so) =
            *(reinterpret_cast<const uint4*>(qh + (size_t)row * DH) + ch);
        *reinterpret_cast<uint4*>(smem + QLo + so) =
            *(reinterpret_cast<const uint4*>(ql + (size_t)row * DH) + ch);
    }

    float m0s = -1e30f, m1s = -1e30f, l0s = 0.0f, l1s = 0.0f;
    float o[8][4];
#pragma unroll
    for (int nt = 0; nt < 8; nt++)
#pragma unroll
        for (int q = 0; q < 4; q++) o[nt][q] = 0.0f;

    for (int kt64 = 0; kt64 < T_SEQ / 64; kt64++) {
        if (kt64 + 1 < T_SEQ / 64) { issue_kv(kt64 + 1, (kt64 + 1) & 1); CP_WAIT1(); }
        else                       { CP_WAIT0(); }
        __syncthreads();
        const char* bp = smem + 32768 + (kt64 & 1) * ATTN_KV_BUF;

        // ---- S = Q K^T (16 x 64 per warp) ----
        float s[8][4];
#pragma unroll
        for (int nt = 0; nt < 8; nt++)
#pragma unroll
            for (int q = 0; q < 4; q++) s[nt][q] = 0.0f;

#pragma unroll
        for (int kt = 0; kt < 4; kt++) {
            const int row = wrow + r;
            const uint32_t o0 = swz(row, kt * 32 + c4);
            const uint32_t o2 = swz(row, kt * 32 + c4 + 16);
            uint32_t qa[4], qb[4];
            qa[0] = *reinterpret_cast<const uint32_t*>(smem + QHo + o0);
            qa[1] = *reinterpret_cast<const uint32_t*>(smem + QHo + o0 + 1024);
            qa[2] = *reinterpret_cast<const uint32_t*>(smem + QHo + o2);
            qa[3] = *reinterpret_cast<const uint32_t*>(smem + QHo + o2 + 1024);
            qb[0] = *reinterpret_cast<const uint32_t*>(smem + QLo + o0);
            qb[1] = *reinterpret_cast<const uint32_t*>(smem + QLo + o0 + 1024);
            qb[2] = *reinterpret_cast<const uint32_t*>(smem + QLo + o2);
            qb[3] = *reinterpret_cast<const uint32_t*>(smem + QLo + o2 + 1024);
#pragma unroll
            for (int nt = 0; nt < 8; nt++) {
                const int rowb = nt * 8 + r;
                const uint32_t ob0 = swz(rowb, kt * 32 + c4);
                const uint32_t ob1 = swz(rowb, kt * 32 + c4 + 16);
                const uint32_t kh0 = *reinterpret_cast<const uint32_t*>(bp + KHo + ob0);
                const uint32_t kh1 = *reinterpret_cast<const uint32_t*>(bp + KHo + ob1);
                const uint32_t kl0 = *reinterpret_cast<const uint32_t*>(bp + KLo + ob0);
                const uint32_t kl1 = *reinterpret_cast<const uint32_t*>(bp + KLo + ob1);
                mma_bf16(s[nt], qa[0], qa[1], qa[2], qa[3], kh0, kh1);
                mma_bf16(s[nt], qa[0], qa[1], qa[2], qa[3], kl0, kl1);
                mma_bf16(s[nt], qb[0], qb[1], qb[2], qb[3], kh0, kh1);
            }
        }

        // ---- online softmax (registers; quad shfl reduce) ----
        float mx0 = -1e30f, mx1 = -1e30f;
#pragma unroll
        for (int nt = 0; nt < 8; nt++) {
            mx0 = fmaxf(mx0, fmaxf(s[nt][0], s[nt][1]));
            mx1 = fmaxf(mx1, fmaxf(s[nt][2], s[nt][3]));
        }
        mx0 = fmaxf(mx0, __shfl_xor_sync(0xffffffffu, mx0, 1));
        mx0 = fmaxf(mx0, __shfl_xor_sync(0xffffffffu, mx0, 2));
        mx1 = fmaxf(mx1, __shfl_xor_sync(0xffffffffu, mx1, 1));
        mx1 = fmaxf(mx1, __shfl_xor_sync(0xffffffffu, mx1, 2));

        const float mn0 = fmaxf(m0s, 8.0f * mx0);   // *sqrt(DH) scale
        const float mn1 = fmaxf(m1s, 8.0f * mx1);
        const float al0 = __expf(m0s - mn0);
        const float al1 = __expf(m1s - mn1);
        m0s = mn0; m1s = mn1;

        float rs0 = 0.0f, rs1 = 0.0f;
#pragma unroll
        for (int nt = 0; nt < 8; nt++) {
            float p0 = __expf(fmaf(8.0f, s[nt][0], -mn0));
            float p1 = __expf(fmaf(8.0f, s[nt][1], -mn0));
            float p2 = __expf(fmaf(8.0f, s[nt][2], -mn1));
            float p3 = __expf(fmaf(8.0f, s[nt][3], -mn1));
            s[nt][0] = p0; s[nt][1] = p1; s[nt][2] = p2; s[nt][3] = p3;
            rs0 += p0 + p1;
            rs1 += p2 + p3;
        }
        rs0 += __shfl_xor_sync(0xffffffffu, rs0, 1);
        rs0 += __shfl_xor_sync(0xffffffffu, rs0, 2);
        rs1 += __shfl_xor_sync(0xffffffffu, rs1, 1);
        rs1 += __shfl_xor_sync(0xffffffffu, rs1, 2);
        l0s = l0s * al0 + rs0;
        l1s = l1s * al1 + rs1;

#pragma unroll
        for (int nt = 0; nt < 8; nt++) {
            o[nt][0] *= al0; o[nt][1] *= al0;
            o[nt][2] *= al1; o[nt][3] *= al1;
        }

        // ---- O += P V : P fragments packed from registers ----
#pragma unroll
        for (int kt = 0; kt < 4; kt++) {
            uint32_t ph[4], pl[4];
            {
                split2(s[2 * kt][0],     s[2 * kt][1],     ph[0], pl[0]);
                split2(s[2 * kt][2],     s[2 * kt][3],     ph[1], pl[1]);
                split2(s[2 * kt + 1][0], s[2 * kt + 1][1], ph[2], pl[2]);
                split2(s[2 * kt + 1][2], s[2 * kt + 1][3], ph[3], pl[3]);
            }
#pragma unroll
            for (int nt = 0; nt < 8; nt++) {
                const int rowv = nt * 8 + r;
                const uint32_t ov0 = swz(rowv, kt * 32 + c4);
                const uint32_t ov1 = swz(rowv, kt * 32 + c4 + 16);
                const uint32_t vh0 = *reinterpret_cast<const uint32_t*>(bp + VHo + ov0);
                const uint32_t vh1 = *reinterpret_cast<const uint32_t*>(bp + VHo + ov1);
                const uint32_t vl0 = *reinterpret_cast<const uint32_t*>(bp + VLo + ov0);
                const uint32_t vl1 = *reinterpret_cast<const uint32_t*>(bp + VLo + ov1);
                mma_bf16(o[nt], ph[0], ph[1], ph[2], ph[3], vh0, vh1);
                mma_bf16(o[nt], ph[0], ph[1], ph[2], ph[3], vl0, vl1);
                mma_bf16(o[nt], pl[0], pl[1], pl[2], pl[3], vh0, vh1);
            }
        }
        __syncthreads();
    }

    // Writeback -> g_oh/g_ol at [b][t][h*64+dh]
    const float li0 = 1.0f / l0s;
    const float li1 = 1.0f / l1s;
    const int b = bh / NH;
    const int h = bh - b * NH;
    const int t_r = t0 + wrow + r;
#pragma unroll
    for (int nt = 0; nt < 8; nt++) {
        const int col = h * DH + nt * 8 + 2 * (lane & 3);
        uint32_t h0, l0, h1, l1;
        split2(o[nt][0] * li0, o[nt][1] * li0, h0, l0);
        split2(o[nt][2] * li1, o[nt][3] * li1, h1, l1);
        size_t p0 = ((size_t)b * T_SEQ + t_r) * DMODEL + col;
        size_t p1 = ((size_t)b * T_SEQ + t_r + 8) * DMODEL + col;
        *reinterpret_cast<uint32_t*>(g_oh + p0) = h0;
        *reinterpret_cast<uint32_t*>(g_ol + p0) = l0;
        *reinterpret_cast<uint32_t*>(g_oh + p1) = h1;
        *reinterpret_cast<uint32_t*>(g_ol + p1) = l1;
    }
}

// ---------------------------------------------------------------------------
extern "C" void kernel_launch(void* const* d_in, const int* in_sizes, int n_in,
                              void* d_out, int out_size) {
    const float* x     = (const float*)d_in[0];   // [4, 2048, 768]
    const float* w_qkv = (const float*)d_in[1];   // [2304, 768]
    const float* w_out = (const float*)d_in[2];   // [768, 768]
    float* out = (float*)d_out;                   // [4, 2048, 768]

    cudaFuncSetAttribute(gemm_mma<0>, cudaFuncAttributeMaxDynamicSharedMemorySize, GEMM_SMEM_BYTES);
    cudaFuncSetAttribute(gemm_mma<1>, cudaFuncAttributeMaxDynamicSharedMemorySize, GEMM_SMEM_BYTES);
    cudaFuncSetAttribute(attn_mma,    cudaFuncAttributeMaxDynamicSharedMemorySize, ATTN_SMEM_BYTES);

    split_all<<<1024, 256>>>(x, w_qkv, w_out);
    gemm_mma<0><<<dim3(64, 18), 256, GEMM_SMEM_BYTES>>>(nullptr);
    attn_mma<<<dim3(16, 48), 256, ATTN_SMEM_BYTES>>>();
    gemm_mma<1><<<dim3(64, 6), 256, GEMM_SMEM_BYTES>>>(out);
}

// round 5
// speedup vs baseline: 3.1399x; 1.0591x over previous
#include <cuda_runtime.h>
#include <cuda_fp16.h>
#include <cstdint>

#define T_SEQ  2048
#define NB     4
#define NH     12
#define DH     64
#define DMODEL 768
#define BHN    (NB * NH)   // 48

// ---------------------------------------------------------------------------
// Device-global scratch (allocation-free rule). fp16 hi/lo splits.
// ---------------------------------------------------------------------------
__device__ uint16_t g_xh[(size_t)NB * T_SEQ * DMODEL];
__device__ uint16_t g_xl[(size_t)NB * T_SEQ * DMODEL];
__device__ uint16_t g_wqh[(size_t)3 * DMODEL * DMODEL];
__device__ uint16_t g_wql[(size_t)3 * DMODEL * DMODEL];
__device__ uint16_t g_woh[(size_t)DMODEL * DMODEL];
__device__ uint16_t g_wol[(size_t)DMODEL * DMODEL];

__device__ uint16_t g_qh[(size_t)BHN * T_SEQ * DH];   // Q pre-scaled by 8
__device__ uint16_t g_ql[(size_t)BHN * T_SEQ * DH];
__device__ uint16_t g_kh[(size_t)BHN * T_SEQ * DH];
__device__ uint16_t g_kl[(size_t)BHN * T_SEQ * DH];
__device__ uint16_t g_vth[(size_t)BHN * DH * T_SEQ];  // V^T: [bh][dh][t]
__device__ uint16_t g_vtl[(size_t)BHN * DH * T_SEQ];

__device__ uint16_t g_oh[(size_t)NB * T_SEQ * DMODEL];
__device__ uint16_t g_ol[(size_t)NB * T_SEQ * DMODEL];

// ---------------------------------------------------------------------------
// Helpers
// ---------------------------------------------------------------------------
__device__ __forceinline__ uint32_t smem_u32(const void* p) {
    uint32_t a;
    asm("{ .reg .u64 t; cvta.to.shared.u64 t, %1; cvt.u32.u64 %0, t; }"
        : "=r"(a) : "l"(p));
    return a;
}

__device__ __forceinline__ void split2(float x0, float x1, uint32_t& h, uint32_t& l) {
    __half2 hh = __floats2half2_rn(x0, x1);
    __half2 ll = __floats2half2_rn(x0 - __low2float(hh), x1 - __high2float(hh));
    h = *reinterpret_cast<uint32_t*>(&hh);
    l = *reinterpret_cast<uint32_t*>(&ll);
}

// m16n8k16 fp16 mma, fp32 accum. A row-major, B col-major.
__device__ __forceinline__ void mma_f16(float* d, const uint32_t* a, uint32_t b0, uint32_t b1) {
    asm volatile(
        "mma.sync.aligned.m16n8k16.row.col.f32.f16.f16.f32 "
        "{%0,%1,%2,%3}, {%4,%5,%6,%7}, {%8,%9}, {%0,%1,%2,%3};"
        : "+f"(d[0]), "+f"(d[1]), "+f"(d[2]), "+f"(d[3])
        : "r"(a[0]), "r"(a[1]), "r"(a[2]), "r"(a[3]), "r"(b0), "r"(b1));
}

// Swizzled smem byte offset within a tile of 128B rows
__device__ __forceinline__ uint32_t swz(int row, int byteoff) {
    return (uint32_t)(row * 128 + (byteoff ^ ((row & 7) << 4)));
}

#define CP_ASYNC16(dst_u32, src_ptr) \
    asm volatile("cp.async.cg.shared.global [%0], [%1], 16;" \
                 :: "r"(dst_u32), "l"(src_ptr) : "memory")
#define CP_COMMIT() asm volatile("cp.async.commit_group;" ::: "memory")
#define CP_WAIT1()  asm volatile("cp.async.wait_group 1;" ::: "memory")
#define CP_WAIT0()  asm volatile("cp.async.wait_group 0;" ::: "memory")

// ---------------------------------------------------------------------------
// Split fp32 -> fp16 (hi, lo)
// ---------------------------------------------------------------------------
__global__ void split_all(const float* __restrict__ x, const float* __restrict__ wq,
                          const float* __restrict__ wo) {
    const int N1 = (NB * T_SEQ * DMODEL) / 4;
    const int N2 = (3 * DMODEL * DMODEL) / 4;
    const int N3 = (DMODEL * DMODEL) / 4;
    const int tot = N1 + N2 + N3;
    for (int i = blockIdx.x * blockDim.x + threadIdx.x; i < tot; i += gridDim.x * blockDim.x) {
        const float4* src;
        uint16_t *dh, *dl;
        int j;
        if (i < N1)           { src = (const float4*)x;  j = i;           dh = g_xh;  dl = g_xl; }
        else if (i < N1 + N2) { src = (const float4*)wq; j = i - N1;      dh = g_wqh; dl = g_wql; }
        else                  { src = (const float4*)wo; j = i - N1 - N2; dh = g_woh; dl = g_wol; }
        float4 v = src[j];
        uint32_t h0, l0, h1, l1;
        split2(v.x, v.y, h0, l0);
        split2(v.z, v.w, h1, l1);
        *reinterpret_cast<uint2*>(dh + 4 * (size_t)j) = uint2{h0, h1};
        *reinterpret_cast<uint2*>(dl + 4 * (size_t)j) = uint2{l0, l1};
    }
}

// ---------------------------------------------------------------------------
// mma.sync split-fp16 GEMM with cp.async double-buffering.
// C[m,n] = sum_k A[m,k]*B[n,k], K=768, CTA tile 128x128, warp tile 32x64.
// ---------------------------------------------------------------------------
#define GEMM_BUF     65536
#define GEMM_SMEM_BYTES (2 * GEMM_BUF)

template <int MODE>
__global__ void __launch_bounds__(256) gemm_mma(float* __restrict__ C) {
    extern __shared__ char smem[];
    const uint32_t sb = smem_u32(smem);
    const int AHo = 0, ALo = 16384, BHo = 32768, BLo = 49152;

    const int tid = threadIdx.x;
    const int lane = tid & 31;
    const int wid = tid >> 5;
    const int r = lane >> 2;
    const int c4 = (lane & 3) * 4;
    const int m0 = blockIdx.x * 128;
    const int by = blockIdx.y;
    const int wm = (wid >> 1) * 32;
    const int wn = (wid & 1) * 64;

    const uint16_t* Ah = (MODE == 0) ? g_xh : g_oh;
    const uint16_t* Al = (MODE == 0) ? g_xl : g_ol;
    const uint16_t* Bh = (MODE == 0) ? g_wqh : g_woh;
    const uint16_t* Bl = (MODE == 0) ? g_wql : g_wol;

    auto issue_stage = [&](int c, int buf) {
        const int k0 = c * 64;
        const uint32_t base = sb + buf * GEMM_BUF;
#pragma unroll
        for (int it = 0; it < 4; it++) {
            const int idx = it * 256 + tid;
            const int row = idx >> 3;
            const int ch = idx & 7;
            const uint32_t so = swz(row, ch * 16);
            CP_ASYNC16(base + AHo + so, Ah + (size_t)(m0 + row) * DMODEL + k0 + ch * 8);
            CP_ASYNC16(base + ALo + so, Al + (size_t)(m0 + row) * DMODEL + k0 + ch * 8);
            const int grow = (MODE == 0) ? ((row & 63) * 36 + by * 2 + (row >> 6))
                                         : (by * 128 + row);
            CP_ASYNC16(base + BHo + so, Bh + (size_t)grow * DMODEL + k0 + ch * 8);
            CP_ASYNC16(base + BLo + so, Bl + (size_t)grow * DMODEL + k0 + ch * 8);
        }
        CP_COMMIT();
    };

    float acc[2][8][4];
#pragma unroll
    for (int mt = 0; mt < 2; mt++)
#pragma unroll
        for (int nt = 0; nt < 8; nt++)
#pragma unroll
            for (int q = 0; q < 4; q++) acc[mt][nt][q] = 0.0f;

    issue_stage(0, 0);

    for (int c = 0; c < 12; c++) {
        if (c + 1 < 12) { issue_stage(c + 1, (c + 1) & 1); CP_WAIT1(); }
        else            { CP_WAIT0(); }
        __syncthreads();
        const char* bp = smem + (c & 1) * GEMM_BUF;

#pragma unroll
        for (int kt = 0; kt < 4; kt++) {
            uint32_t aH[2][4], aL[2][4];
#pragma unroll
            for (int mt = 0; mt < 2; mt++) {
                const int row = wm + mt * 16 + r;
                const uint32_t o0 = swz(row, kt * 32 + c4);
                const uint32_t o2 = swz(row, kt * 32 + c4 + 16);
                aH[mt][0] = *reinterpret_cast<const uint32_t*>(bp + AHo + o0);
                aH[mt][1] = *reinterpret_cast<const uint32_t*>(bp + AHo + o0 + 1024);
                aH[mt][2] = *reinterpret_cast<const uint32_t*>(bp + AHo + o2);
                aH[mt][3] = *reinterpret_cast<const uint32_t*>(bp + AHo + o2 + 1024);
                aL[mt][0] = *reinterpret_cast<const uint32_t*>(bp + ALo + o0);
                aL[mt][1] = *reinterpret_cast<const uint32_t*>(bp + ALo + o0 + 1024);
                aL[mt][2] = *reinterpret_cast<const uint32_t*>(bp + ALo + o2);
                aL[mt][3] = *reinterpret_cast<const uint32_t*>(bp + ALo + o2 + 1024);
            }
#pragma unroll
            for (int nt = 0; nt < 8; nt++) {
                const int rowb = wn + nt * 8 + r;
                const uint32_t ob0 = swz(rowb, kt * 32 + c4);
                const uint32_t ob1 = swz(rowb, kt * 32 + c4 + 16);
                const uint32_t bh0 = *reinterpret_cast<const uint32_t*>(bp + BHo + ob0);
                const uint32_t bh1 = *reinterpret_cast<const uint32_t*>(bp + BHo + ob1);
                const uint32_t bl0 = *reinterpret_cast<const uint32_t*>(bp + BLo + ob0);
                const uint32_t bl1 = *reinterpret_cast<const uint32_t*>(bp + BLo + ob1);
                // term-major: consecutive MMAs hit different accumulators
                mma_f16(acc[0][nt], aH[0], bh0, bh1);
                mma_f16(acc[1][nt], aH[1], bh0, bh1);
                mma_f16(acc[0][nt], aH[0], bl0, bl1);
                mma_f16(acc[1][nt], aH[1], bl0, bl1);
                mma_f16(acc[0][nt], aL[0], bh0, bh1);
                mma_f16(acc[1][nt], aL[1], bh0, bh1);
            }
        }
        __syncthreads();
    }

    // Epilogue
#pragma unroll
    for (int mt = 0; mt < 2; mt++) {
        const int mrow = m0 + wm + mt * 16 + r;
#pragma unroll
        for (int nt = 0; nt < 8; nt++) {
            const int nl = wn + nt * 8 + 2 * (lane & 3);
            float d0 = acc[mt][nt][0], d1 = acc[mt][nt][1];
            float d2 = acc[mt][nt][2], d3 = acc[mt][nt][3];
            if (MODE == 0) {
                const int koff = by * 2 + (nl >> 6);
                const int dh = nl & 63;
                const int k3 = koff / 12;
                const int h = koff - 12 * k3;
                const int b = mrow >> 11;
                const int t = mrow & 2047;
                const int bhI = b * NH + h;
                if (k3 == 0) { d0 *= 8.0f; d1 *= 8.0f; d2 *= 8.0f; d3 *= 8.0f; }  // fold sqrt(DH)
                uint32_t h0, l0, h1, l1;
                split2(d0, d1, h0, l0);
                split2(d2, d3, h1, l1);
                if (k3 == 0) {
                    size_t p0 = ((size_t)bhI * T_SEQ + t) * DH + dh;
                    size_t p1 = ((size_t)bhI * T_SEQ + t + 8) * DH + dh;
                    *reinterpret_cast<uint32_t*>(g_qh + p0) = h0;
                    *reinterpret_cast<uint32_t*>(g_ql + p0) = l0;
                    *reinterpret_cast<uint32_t*>(g_qh + p1) = h1;
                    *reinterpret_cast<uint32_t*>(g_ql + p1) = l1;
                } else if (k3 == 1) {
                    size_t p0 = ((size_t)bhI * T_SEQ + t) * DH + dh;
                    size_t p1 = ((size_t)bhI * T_SEQ + t + 8) * DH + dh;
                    *reinterpret_cast<uint32_t*>(g_kh + p0) = h0;
                    *reinterpret_cast<uint32_t*>(g_kl + p0) = l0;
                    *reinterpret_cast<uint32_t*>(g_kh + p1) = h1;
                    *reinterpret_cast<uint32_t*>(g_kl + p1) = l1;
                } else {
                    size_t q0 = ((size_t)bhI * DH + dh) * T_SEQ + t;
                    size_t q1 = ((size_t)bhI * DH + dh + 1) * T_SEQ + t;
                    g_vth[q0] = (uint16_t)h0;      g_vth[q1] = (uint16_t)(h0 >> 16);
                    g_vtl[q0] = (uint16_t)l0;      g_vtl[q1] = (uint16_t)(l0 >> 16);
                    g_vth[q0 + 8] = (uint16_t)h1;  g_vth[q1 + 8] = (uint16_t)(h1 >> 16);
                    g_vtl[q0 + 8] = (uint16_t)l1;  g_vtl[q1 + 8] = (uint16_t)(l1 >> 16);
                }
            } else {
                float2 p0{d0, d1}, p1{d2, d3};
                *reinterpret_cast<float2*>(C + (size_t)mrow * DMODEL + by * 128 + nl) = p0;
                *reinterpret_cast<float2*>(C + (size_t)(mrow + 8) * DMODEL + by * 128 + nl) = p1;
            }
        }
    }
}

// ---------------------------------------------------------------------------
// Flash attention: 128 threads (4 warps), warp tile 32 q-rows x 64 keys (mt=2),
// K/V fragments shared across mt; cp.async double-buffered KV; 2 CTAs/SM.
// Q is pre-scaled by 8, so S needs no extra scale.
// ---------------------------------------------------------------------------
#define ATTN_KV_BUF   32768
#define ATTN_SMEM_BYTES (32768 + 2 * ATTN_KV_BUF)   // Q(32K) + 2 KV stages

__global__ void __launch_bounds__(128) attn_mma() {
    extern __shared__ char smem[];
    const uint32_t sb = smem_u32(smem);
    const int QHo = 0, QLo = 16384;
    const int KHo = 0, KLo = 8192, VHo = 16384, VLo = 24576;   // within KV stage

    const int tid = threadIdx.x;
    const int lane = tid & 31;
    const int wid = tid >> 5;          // 0..3
    const int r = lane >> 2;
    const int c4 = (lane & 3) * 4;
    const int bh = blockIdx.y;
    const int t0 = blockIdx.x * 128;
    const int wrow = wid * 32;         // 32 q-rows per warp

    const uint16_t* kh = g_kh + (size_t)bh * T_SEQ * DH;
    const uint16_t* kl = g_kl + (size_t)bh * T_SEQ * DH;
    const uint16_t* vh = g_vth + (size_t)bh * DH * T_SEQ;
    const uint16_t* vl = g_vtl + (size_t)bh * DH * T_SEQ;

    auto issue_kv = [&](int kt, int buf) {
        const uint32_t base = sb + 32768 + buf * ATTN_KV_BUF;
#pragma unroll
        for (int it = 0; it < 4; it++) {
            const int idx = it * 128 + tid;
            const int row = idx >> 3;
            const int ch = idx & 7;
            const uint32_t so = swz(row, ch * 16);
            CP_ASYNC16(base + KHo + so, kh + (size_t)(kt * 64 + row) * DH + ch * 8);
            CP_ASYNC16(base + KLo + so, kl + (size_t)(kt * 64 + row) * DH + ch * 8);
            CP_ASYNC16(base + VHo + so, vh + (size_t)row * T_SEQ + kt * 64 + ch * 8);
            CP_ASYNC16(base + VLo + so, vl + (size_t)row * T_SEQ + kt * 64 + ch * 8);
        }
        CP_COMMIT();
    };

    issue_kv(0, 0);

    // Stage Q hi/lo tiles [128][64]
    const uint16_t* qhp = g_qh + ((size_t)bh * T_SEQ + t0) * DH;
    const uint16_t* qlp = g_ql + ((size_t)bh * T_SEQ + t0) * DH;
#pragma unroll
    for (int it = 0; it < 8; it++) {
        const int idx = it * 128 + tid;
        const int row = idx >> 3;
        const int ch = idx & 7;
        const uint32_t so = swz(row, ch * 16);
        *reinterpret_cast<uint4*>(smem + QHo + so) =
            *(reinterpret_cast<const uint4*>(qhp + (size_t)row * DH) + ch);
        *reinterpret_cast<uint4*>(smem + QLo + so) =
            *(reinterpret_cast<const uint4*>(qlp + (size_t)row * DH) + ch);
    }

    float mS[2][2], lS[2][2];
#pragma unroll
    for (int mt = 0; mt < 2; mt++) { mS[mt][0] = mS[mt][1] = -1e30f; lS[mt][0] = lS[mt][1] = 0.0f; }

    float o[2][8][4];
#pragma unroll
    for (int mt = 0; mt < 2; mt++)
#pragma unroll
        for (int nt = 0; nt < 8; nt++)
#pragma unroll
            for (int q = 0; q < 4; q++) o[mt][nt][q] = 0.0f;

    for (int kt64 = 0; kt64 < T_SEQ / 64; kt64++) {
        if (kt64 + 1 < T_SEQ / 64) { issue_kv(kt64 + 1, (kt64 + 1) & 1); CP_WAIT1(); }
        else                       { CP_WAIT0(); }
        __syncthreads();
        const char* bp = smem + 32768 + (kt64 & 1) * ATTN_KV_BUF;

        // ---- S = Q K^T (32 x 64 per warp) ----
        float s[2][8][4];
#pragma unroll
        for (int mt = 0; mt < 2; mt++)
#pragma unroll
            for (int nt = 0; nt < 8; nt++)
#pragma unroll
                for (int q = 0; q < 4; q++) s[mt][nt][q] = 0.0f;

#pragma unroll
        for (int kt = 0; kt < 4; kt++) {
            uint32_t qa[2][4], qb[2][4];
#pragma unroll
            for (int mt = 0; mt < 2; mt++) {
                const int row = wrow + mt * 16 + r;
                const uint32_t o0 = swz(row, kt * 32 + c4);
                const uint32_t o2 = swz(row, kt * 32 + c4 + 16);
                qa[mt][0] = *reinterpret_cast<const uint32_t*>(smem + QHo + o0);
                qa[mt][1] = *reinterpret_cast<const uint32_t*>(smem + QHo + o0 + 1024);
                qa[mt][2] = *reinterpret_cast<const uint32_t*>(smem + QHo + o2);
                qa[mt][3] = *reinterpret_cast<const uint32_t*>(smem + QHo + o2 + 1024);
                qb[mt][0] = *reinterpret_cast<const uint32_t*>(smem + QLo + o0);
                qb[mt][1] = *reinterpret_cast<const uint32_t*>(smem + QLo + o0 + 1024);
                qb[mt][2] = *reinterpret_cast<const uint32_t*>(smem + QLo + o2);
                qb[mt][3] = *reinterpret_cast<const uint32_t*>(smem + QLo + o2 + 1024);
            }
#pragma unroll
            for (int nt = 0; nt < 8; nt++) {
                const int rowb = nt * 8 + r;
                const uint32_t ob0 = swz(rowb, kt * 32 + c4);
                const uint32_t ob1 = swz(rowb, kt * 32 + c4 + 16);
                const uint32_t kh0 = *reinterpret_cast<const uint32_t*>(bp + KHo + ob0);
                const uint32_t kh1 = *reinterpret_cast<const uint32_t*>(bp + KHo + ob1);
                const uint32_t kl0 = *reinterpret_cast<const uint32_t*>(bp + KLo + ob0);
                const uint32_t kl1 = *reinterpret_cast<const uint32_t*>(bp + KLo + ob1);
                mma_f16(s[0][nt], qa[0], kh0, kh1);
                mma_f16(s[1][nt], qa[1], kh0, kh1);
                mma_f16(s[0][nt], qa[0], kl0, kl1);
                mma_f16(s[1][nt], qa[1], kl0, kl1);
                mma_f16(s[0][nt], qb[0], kh0, kh1);
                mma_f16(s[1][nt], qb[1], kh0, kh1);
            }
        }

        // ---- online softmax per mt (registers; quad shfl reduce) ----
        float alpha[2][2];
#pragma unroll
        for (int mt = 0; mt < 2; mt++) {
            float mx0 = -1e30f, mx1 = -1e30f;
#pragma unroll
            for (int nt = 0; nt < 8; nt++) {
                mx0 = fmaxf(mx0, fmaxf(s[mt][nt][0], s[mt][nt][1]));
                mx1 = fmaxf(mx1, fmaxf(s[mt][nt][2], s[mt][nt][3]));
            }
            mx0 = fmaxf(mx0, __shfl_xor_sync(0xffffffffu, mx0, 1));
            mx0 = fmaxf(mx0, __shfl_xor_sync(0xffffffffu, mx0, 2));
            mx1 = fmaxf(mx1, __shfl_xor_sync(0xffffffffu, mx1, 1));
            mx1 = fmaxf(mx1, __shfl_xor_sync(0xffffffffu, mx1, 2));

            const float mn0 = fmaxf(mS[mt][0], mx0);
            const float mn1 = fmaxf(mS[mt][1], mx1);
            alpha[mt][0] = __expf(mS[mt][0] - mn0);
            alpha[mt][1] = __expf(mS[mt][1] - mn1);
            mS[mt][0] = mn0; mS[mt][1] = mn1;

            float rs0 = 0.0f, rs1 = 0.0f;
#pragma unroll
            for (int nt = 0; nt < 8; nt++) {
                float p0 = __expf(s[mt][nt][0] - mn0);
                float p1 = __expf(s[mt][nt][1] - mn0);
                float p2 = __expf(s[mt][nt][2] - mn1);
                float p3 = __expf(s[mt][nt][3] - mn1);
                s[mt][nt][0] = p0; s[mt][nt][1] = p1; s[mt][nt][2] = p2; s[mt][nt][3] = p3;
                rs0 += p0 + p1;
                rs1 += p2 + p3;
            }
            rs0 += __shfl_xor_sync(0xffffffffu, rs0, 1);
            rs0 += __shfl_xor_sync(0xffffffffu, rs0, 2);
            rs1 += __shfl_xor_sync(0xffffffffu, rs1, 1);
            rs1 += __shfl_xor_sync(0xffffffffu, rs1, 2);
            lS[mt][0] = lS[mt][0] * alpha[mt][0] + rs0;
            lS[mt][1] = lS[mt][1] * alpha[mt][1] + rs1;

#pragma unroll
            for (int nt = 0; nt < 8; nt++) {
                o[mt][nt][0] *= alpha[mt][0]; o[mt][nt][1] *= alpha[mt][0];
                o[mt][nt][2] *= alpha[mt][1]; o[mt][nt][3] *= alpha[mt][1];
            }
        }

        // ---- O += P V : P fragments packed from registers, V shared across mt ----
#pragma unroll
        for (int kt = 0; kt < 4; kt++) {
            uint32_t ph[2][4], pl[2][4];
#pragma unroll
            for (int mt = 0; mt < 2; mt++) {
                split2(s[mt][2 * kt][0],     s[mt][2 * kt][1],     ph[mt][0], pl[mt][0]);
                split2(s[mt][2 * kt][2],     s[mt][2 * kt][3],     ph[mt][1], pl[mt][1]);
                split2(s[mt][2 * kt + 1][0], s[mt][2 * kt + 1][1], ph[mt][2], pl[mt][2]);
                split2(s[mt][2 * kt + 1][2], s[mt][2 * kt + 1][3], ph[mt][3], pl[mt][3]);
            }
#pragma unroll
            for (int nt = 0; nt < 8; nt++) {
                const int rowv = nt * 8 + r;
                const uint32_t ov0 = swz(rowv, kt * 32 + c4);
                const uint32_t ov1 = swz(rowv, kt * 32 + c4 + 16);
                const uint32_t vh0 = *reinterpret_cast<const uint32_t*>(bp + VHo + ov0);
                const uint32_t vh1 = *reinterpret_cast<const uint32_t*>(bp + VHo + ov1);
                const uint32_t vl0 = *reinterpret_cast<const uint32_t*>(bp + VLo + ov0);
                const uint32_t vl1 = *reinterpret_cast<const uint32_t*>(bp + VLo + ov1);
                mma_f16(o[0][nt], ph[0], vh0, vh1);
                mma_f16(o[1][nt], ph[1], vh0, vh1);
                mma_f16(o[0][nt], ph[0], vl0, vl1);
                mma_f16(o[1][nt], ph[1], vl0, vl1);
                mma_f16(o[0][nt], pl[0], vh0, vh1);
                mma_f16(o[1][nt], pl[1], vh0, vh1);
            }
        }
        __syncthreads();
    }

    // Writeback -> g_oh/g_ol at [b][t][h*64+dh]
    const int b = bh / NH;
    const int h = bh - b * NH;
#pragma unroll
    for (int mt = 0; mt < 2; mt++) {
        const float li0 = 1.0f / lS[mt][0];
        const float li1 = 1.0f / lS[mt][1];
        const int t_r = t0 + wrow + mt * 16 + r;
#pragma unroll
        for (int nt = 0; nt < 8; nt++) {
            const int col = h * DH + nt * 8 + 2 * (lane & 3);
            uint32_t h0, l0, h1, l1;
            split2(o[mt][nt][0] * li0, o[mt][nt][1] * li0, h0, l0);
            split2(o[mt][nt][2] * li1, o[mt][nt][3] * li1, h1, l1);
            size_t p0 = ((size_t)b * T_SEQ + t_r) * DMODEL + col;
            size_t p1 = ((size_t)b * T_SEQ + t_r + 8) * DMODEL + col;
            *reinterpret_cast<uint32_t*>(g_oh + p0) = h0;
            *reinterpret_cast<uint32_t*>(g_ol + p0) = l0;
            *reinterpret_cast<uint32_t*>(g_oh + p1) = h1;
            *reinterpret_cast<uint32_t*>(g_ol + p1) = l1;
        }
    }
}

// ---------------------------------------------------------------------------
extern "C" void kernel_launch(void* const* d_in, const int* in_sizes, int n_in,
                              void* d_out, int out_size) {
    const float* x     = (const float*)d_in[0];   // [4, 2048, 768]
    const float* w_qkv = (const float*)d_in[1];   // [2304, 768]
    const float* w_out = (const float*)d_in[2];   // [768, 768]
    float* out = (float*)d_out;                   // [4, 2048, 768]

    cudaFuncSetAttribute(gemm_mma<0>, cudaFuncAttributeMaxDynamicSharedMemorySize, GEMM_SMEM_BYTES);
    cudaFuncSetAttribute(gemm_mma<1>, cudaFuncAttributeMaxDynamicSharedMemorySize, GEMM_SMEM_BYTES);
    cudaFuncSetAttribute(attn_mma,    cudaFuncAttributeMaxDynamicSharedMemorySize, ATTN_SMEM_BYTES);

    split_all<<<1024, 256>>>(x, w_qkv, w_out);
    gemm_mma<0><<<dim3(64, 18), 256, GEMM_SMEM_BYTES>>>(nullptr);
    attn_mma<<<dim3(16, 48), 128, ATTN_SMEM_BYTES>>>();
    gemm_mma<1><<<dim3(64, 6), 256, GEMM_SMEM_BYTES>>>(out);
}

// round 6
// speedup vs baseline: 3.1731x; 1.0106x over previous
#include <cuda_runtime.h>
#include <cuda_fp16.h>
#include <cstdint>

#define T_SEQ  2048
#define NB     4
#define NH     12
#define DH     64
#define DMODEL 768
#define BHN    (NB * NH)   // 48

// 8 * log2(e): softmax computed in base-2 domain
#define QSCALE 11.5415603f

// ---------------------------------------------------------------------------
// Device-global scratch (allocation-free rule). fp16 hi/lo splits.
// ---------------------------------------------------------------------------
__device__ uint16_t g_xh[(size_t)NB * T_SEQ * DMODEL];
__device__ uint16_t g_xl[(size_t)NB * T_SEQ * DMODEL];
__device__ uint16_t g_wqh[(size_t)3 * DMODEL * DMODEL];
__device__ uint16_t g_wql[(size_t)3 * DMODEL * DMODEL];
__device__ uint16_t g_woh[(size_t)DMODEL * DMODEL];
__device__ uint16_t g_wol[(size_t)DMODEL * DMODEL];

__device__ uint16_t g_qh[(size_t)BHN * T_SEQ * DH];   // Q pre-scaled by 8*log2(e)
__device__ uint16_t g_ql[(size_t)BHN * T_SEQ * DH];
__device__ uint16_t g_kh[(size_t)BHN * T_SEQ * DH];
__device__ uint16_t g_kl[(size_t)BHN * T_SEQ * DH];
__device__ uint16_t g_vth[(size_t)BHN * DH * T_SEQ];  // V^T: [bh][dh][t]
__device__ uint16_t g_vtl[(size_t)BHN * DH * T_SEQ];

__device__ uint16_t g_oh[(size_t)NB * T_SEQ * DMODEL];
__device__ uint16_t g_ol[(size_t)NB * T_SEQ * DMODEL];

// ---------------------------------------------------------------------------
// Helpers
// ---------------------------------------------------------------------------
__device__ __forceinline__ uint32_t smem_u32(const void* p) {
    uint32_t a;
    asm("{ .reg .u64 t; cvta.to.shared.u64 t, %1; cvt.u32.u64 %0, t; }"
        : "=r"(a) : "l"(p));
    return a;
}

__device__ __forceinline__ float ex2f(float x) {
    float y;
    asm("ex2.approx.f32 %0, %1;" : "=f"(y) : "f"(x));
    return y;
}

__device__ __forceinline__ void split2(float x0, float x1, uint32_t& h, uint32_t& l) {
    __half2 hh = __floats2half2_rn(x0, x1);
    __half2 ll = __floats2half2_rn(x0 - __low2float(hh), x1 - __high2float(hh));
    h = *reinterpret_cast<uint32_t*>(&hh);
    l = *reinterpret_cast<uint32_t*>(&ll);
}

// m16n8k16 fp16 mma, fp32 accum. A row-major, B col-major.
__device__ __forceinline__ void mma_f16(float* d, const uint32_t* a, uint32_t b0, uint32_t b1) {
    asm volatile(
        "mma.sync.aligned.m16n8k16.row.col.f32.f16.f16.f32 "
        "{%0,%1,%2,%3}, {%4,%5,%6,%7}, {%8,%9}, {%0,%1,%2,%3};"
        : "+f"(d[0]), "+f"(d[1]), "+f"(d[2]), "+f"(d[3])
        : "r"(a[0]), "r"(a[1]), "r"(a[2]), "r"(a[3]), "r"(b0), "r"(b1));
}

// Swizzled smem byte offset within a tile of 128B rows
__device__ __forceinline__ uint32_t swz(int row, int byteoff) {
    return (uint32_t)(row * 128 + (byteoff ^ ((row & 7) << 4)));
}

#define CP_ASYNC16(dst_u32, src_ptr) \
    asm volatile("cp.async.cg.shared.global [%0], [%1], 16;" \
                 :: "r"(dst_u32), "l"(src_ptr) : "memory")
#define CP_COMMIT() asm volatile("cp.async.commit_group;" ::: "memory")
#define CP_WAIT1()  asm volatile("cp.async.wait_group 1;" ::: "memory")
#define CP_WAIT0()  asm volatile("cp.async.wait_group 0;" ::: "memory")

// ---------------------------------------------------------------------------
// Split fp32 -> fp16 (hi, lo)
// ---------------------------------------------------------------------------
__global__ void split_all(const float* __restrict__ x, const float* __restrict__ wq,
                          const float* __restrict__ wo) {
    const int N1 = (NB * T_SEQ * DMODEL) / 4;
    const int N2 = (3 * DMODEL * DMODEL) / 4;
    const int N3 = (DMODEL * DMODEL) / 4;
    const int tot = N1 + N2 + N3;
    for (int i = blockIdx.x * blockDim.x + threadIdx.x; i < tot; i += gridDim.x * blockDim.x) {
        const float4* src;
        uint16_t *dh, *dl;
        int j;
        if (i < N1)           { src = (const float4*)x;  j = i;           dh = g_xh;  dl = g_xl; }
        else if (i < N1 + N2) { src = (const float4*)wq; j = i - N1;      dh = g_wqh; dl = g_wql; }
        else                  { src = (const float4*)wo; j = i - N1 - N2; dh = g_woh; dl = g_wol; }
        float4 v = src[j];
        uint32_t h0, l0, h1, l1;
        split2(v.x, v.y, h0, l0);
        split2(v.z, v.w, h1, l1);
        *reinterpret_cast<uint2*>(dh + 4 * (size_t)j) = uint2{h0, h1};
        *reinterpret_cast<uint2*>(dl + 4 * (size_t)j) = uint2{l0, l1};
    }
}

// ---------------------------------------------------------------------------
// mma.sync split-fp16 GEMM, warp tile 64x64, cp.async double-buffered.
// MODE 0: CTAM=256, 8 warps. MODE 1: CTAM=128, 4 warps.
// ---------------------------------------------------------------------------
template <int MODE, int CTAM, int NTHR>
__global__ void __launch_bounds__(NTHR, 1) gemm_mma(float* __restrict__ C) {
    extern __shared__ char smem[];
    const uint32_t sb = smem_u32(smem);
    constexpr int ABYTES = CTAM * 128;                 // one A split tile
    constexpr int AHo = 0, ALo = ABYTES, BHo = 2 * ABYTES, BLo = 2 * ABYTES + 16384;
    constexpr int STAGE = 2 * ABYTES + 32768;

    const int tid = threadIdx.x;
    const int lane = tid & 31;
    const int wid = tid >> 5;
    const int r = lane >> 2;
    const int c4 = (lane & 3) * 4;
    const int m0 = blockIdx.x * CTAM;
    const int by = blockIdx.y;
    const int wm = (wid >> 1) * 64;     // 64 m-rows per warp
    const int wn = (wid & 1) * 64;      // 64 n-cols per warp

    const uint16_t* Ah = (MODE == 0) ? g_xh : g_oh;
    const uint16_t* Al = (MODE == 0) ? g_xl : g_ol;
    const uint16_t* Bh = (MODE == 0) ? g_wqh : g_woh;
    const uint16_t* Bl = (MODE == 0) ? g_wql : g_wol;

    auto issue_stage = [&](int c, int buf) {
        const int k0 = c * 64;
        const uint32_t base = sb + buf * STAGE;
#pragma unroll
        for (int it = 0; it < CTAM * 8 / NTHR; it++) {
            const int idx = it * NTHR + tid;
            const int row = idx >> 3;
            const int ch = idx & 7;
            const uint32_t so = swz(row, ch * 16);
            CP_ASYNC16(base + AHo + so, Ah + (size_t)(m0 + row) * DMODEL + k0 + ch * 8);
            CP_ASYNC16(base + ALo + so, Al + (size_t)(m0 + row) * DMODEL + k0 + ch * 8);
        }
#pragma unroll
        for (int it = 0; it < 1024 / NTHR; it++) {
            const int idx = it * NTHR + tid;
            const int row = idx >> 3;
            const int ch = idx & 7;
            const uint32_t so = swz(row, ch * 16);
            const int grow = (MODE == 0) ? ((row & 63) * 36 + by * 2 + (row >> 6))
                                         : (by * 128 + row);
            CP_ASYNC16(base + BHo + so, Bh + (size_t)grow * DMODEL + k0 + ch * 8);
            CP_ASYNC16(base + BLo + so, Bl + (size_t)grow * DMODEL + k0 + ch * 8);
        }
        CP_COMMIT();
    };

    float acc[4][8][4];
#pragma unroll
    for (int mt = 0; mt < 4; mt++)
#pragma unroll
        for (int nt = 0; nt < 8; nt++)
#pragma unroll
            for (int q = 0; q < 4; q++) acc[mt][nt][q] = 0.0f;

    issue_stage(0, 0);

    for (int c = 0; c < 12; c++) {
        if (c + 1 < 12) { issue_stage(c + 1, (c + 1) & 1); CP_WAIT1(); }
        else            { CP_WAIT0(); }
        __syncthreads();
        const char* bp = smem + (c & 1) * STAGE;

#pragma unroll
        for (int kt = 0; kt < 4; kt++) {
            uint32_t aH[4][4], aL[4][4];
#pragma unroll
            for (int mt = 0; mt < 4; mt++) {
                const int row = wm + mt * 16 + r;
                const uint32_t o0 = swz(row, kt * 32 + c4);
                const uint32_t o2 = swz(row, kt * 32 + c4 + 16);
                aH[mt][0] = *reinterpret_cast<const uint32_t*>(bp + AHo + o0);
                aH[mt][1] = *reinterpret_cast<const uint32_t*>(bp + AHo + o0 + 1024);
                aH[mt][2] = *reinterpret_cast<const uint32_t*>(bp + AHo + o2);
                aH[mt][3] = *reinterpret_cast<const uint32_t*>(bp + AHo + o2 + 1024);
                aL[mt][0] = *reinterpret_cast<const uint32_t*>(bp + ALo + o0);
                aL[mt][1] = *reinterpret_cast<const uint32_t*>(bp + ALo + o0 + 1024);
                aL[mt][2] = *reinterpret_cast<const uint32_t*>(bp + ALo + o2);
                aL[mt][3] = *reinterpret_cast<const uint32_t*>(bp + ALo + o2 + 1024);
            }
#pragma unroll
            for (int nt = 0; nt < 8; nt++) {
                const int rowb = wn + nt * 8 + r;
                const uint32_t ob0 = swz(rowb, kt * 32 + c4);
                const uint32_t ob1 = swz(rowb, kt * 32 + c4 + 16);
                const uint32_t bh0 = *reinterpret_cast<const uint32_t*>(bp + BHo + ob0);
                const uint32_t bh1 = *reinterpret_cast<const uint32_t*>(bp + BHo + ob1);
                const uint32_t bl0 = *reinterpret_cast<const uint32_t*>(bp + BLo + ob0);
                const uint32_t bl1 = *reinterpret_cast<const uint32_t*>(bp + BLo + ob1);
#pragma unroll
                for (int mt = 0; mt < 4; mt++) mma_f16(acc[mt][nt], aH[mt], bh0, bh1);
#pragma unroll
                for (int mt = 0; mt < 4; mt++) mma_f16(acc[mt][nt], aH[mt], bl0, bl1);
#pragma unroll
                for (int mt = 0; mt < 4; mt++) mma_f16(acc[mt][nt], aL[mt], bh0, bh1);
            }
        }
        __syncthreads();
    }

    // Epilogue
#pragma unroll
    for (int mt = 0; mt < 4; mt++) {
        const int mrow = m0 + wm + mt * 16 + r;
#pragma unroll
        for (int nt = 0; nt < 8; nt++) {
            const int nl = wn + nt * 8 + 2 * (lane & 3);
            float d0 = acc[mt][nt][0], d1 = acc[mt][nt][1];
            float d2 = acc[mt][nt][2], d3 = acc[mt][nt][3];
            if (MODE == 0) {
                const int koff = by * 2 + (nl >> 6);
                const int dh = nl & 63;
                const int k3 = koff / 12;
                const int h = koff - 12 * k3;
                const int b = mrow >> 11;
                const int t = mrow & 2047;
                const int bhI = b * NH + h;
                if (k3 == 0) { d0 *= QSCALE; d1 *= QSCALE; d2 *= QSCALE; d3 *= QSCALE; }
                uint32_t h0, l0, h1, l1;
                split2(d0, d1, h0, l0);
                split2(d2, d3, h1, l1);
                if (k3 == 0) {
                    size_t p0 = ((size_t)bhI * T_SEQ + t) * DH + dh;
                    size_t p1 = ((size_t)bhI * T_SEQ + t + 8) * DH + dh;
                    *reinterpret_cast<uint32_t*>(g_qh + p0) = h0;
                    *reinterpret_cast<uint32_t*>(g_ql + p0) = l0;
                    *reinterpret_cast<uint32_t*>(g_qh + p1) = h1;
                    *reinterpret_cast<uint32_t*>(g_ql + p1) = l1;
                } else if (k3 == 1) {
                    size_t p0 = ((size_t)bhI * T_SEQ + t) * DH + dh;
                    size_t p1 = ((size_t)bhI * T_SEQ + t + 8) * DH + dh;
                    *reinterpret_cast<uint32_t*>(g_kh + p0) = h0;
                    *reinterpret_cast<uint32_t*>(g_kl + p0) = l0;
                    *reinterpret_cast<uint32_t*>(g_kh + p1) = h1;
                    *reinterpret_cast<uint32_t*>(g_kl + p1) = l1;
                } else {
                    size_t q0 = ((size_t)bhI * DH + dh) * T_SEQ + t;
                    size_t q1 = ((size_t)bhI * DH + dh + 1) * T_SEQ + t;
                    g_vth[q0] = (uint16_t)h0;      g_vth[q1] = (uint16_t)(h0 >> 16);
                    g_vtl[q0] = (uint16_t)l0;      g_vtl[q1] = (uint16_t)(l0 >> 16);
                    g_vth[q0 + 8] = (uint16_t)h1;  g_vth[q1 + 8] = (uint16_t)(h1 >> 16);
                    g_vtl[q0 + 8] = (uint16_t)l1;  g_vtl[q1 + 8] = (uint16_t)(l1 >> 16);
                }
            } else {
                float2 p0{d0, d1}, p1{d2, d3};
                *reinterpret_cast<float2*>(C + (size_t)mrow * DMODEL + by * 128 + nl) = p0;
                *reinterpret_cast<float2*>(C + (size_t)(mrow + 8) * DMODEL + by * 128 + nl) = p1;
            }
        }
    }
}

// ---------------------------------------------------------------------------
// Flash attention: 128 threads (4 warps), warp tile 32 q-rows x 64 keys,
// cp.async double-buffered KV, softmax in base-2 (Q pre-scaled by 8*log2e).
// ---------------------------------------------------------------------------
#define ATTN_KV_BUF   32768
#define ATTN_SMEM_BYTES (32768 + 2 * ATTN_KV_BUF)   // Q(32K) + 2 KV stages

__global__ void __launch_bounds__(128) attn_mma() {
    extern __shared__ char smem[];
    const uint32_t sb = smem_u32(smem);
    const int QHo = 0, QLo = 16384;
    const int KHo = 0, KLo = 8192, VHo = 16384, VLo = 24576;   // within KV stage

    const int tid = threadIdx.x;
    const int lane = tid & 31;
    const int wid = tid >> 5;          // 0..3
    const int r = lane >> 2;
    const int c4 = (lane & 3) * 4;
    const int bh = blockIdx.y;
    const int t0 = blockIdx.x * 128;
    const int wrow = wid * 32;         // 32 q-rows per warp

    const uint16_t* kh = g_kh + (size_t)bh * T_SEQ * DH;
    const uint16_t* kl = g_kl + (size_t)bh * T_SEQ * DH;
    const uint16_t* vh = g_vth + (size_t)bh * DH * T_SEQ;
    const uint16_t* vl = g_vtl + (size_t)bh * DH * T_SEQ;

    auto issue_kv = [&](int kt, int buf) {
        const uint32_t base = sb + 32768 + buf * ATTN_KV_BUF;
#pragma unroll
        for (int it = 0; it < 4; it++) {
            const int idx = it * 128 + tid;
            const int row = idx >> 3;
            const int ch = idx & 7;
            const uint32_t so = swz(row, ch * 16);
            CP_ASYNC16(base + KHo + so, kh + (size_t)(kt * 64 + row) * DH + ch * 8);
            CP_ASYNC16(base + KLo + so, kl + (size_t)(kt * 64 + row) * DH + ch * 8);
            CP_ASYNC16(base + VHo + so, vh + (size_t)row * T_SEQ + kt * 64 + ch * 8);
            CP_ASYNC16(base + VLo + so, vl + (size_t)row * T_SEQ + kt * 64 + ch * 8);
        }
        CP_COMMIT();
    };

    issue_kv(0, 0);

    // Stage Q hi/lo tiles [128][64]
    const uint16_t* qhp = g_qh + ((size_t)bh * T_SEQ + t0) * DH;
    const uint16_t* qlp = g_ql + ((size_t)bh * T_SEQ + t0) * DH;
#pragma unroll
    for (int it = 0; it < 8; it++) {
        const int idx = it * 128 + tid;
        const int row = idx >> 3;
        const int ch = idx & 7;
        const uint32_t so = swz(row, ch * 16);
        *reinterpret_cast<uint4*>(smem + QHo + so) =
            *(reinterpret_cast<const uint4*>(qhp + (size_t)row * DH) + ch);
        *reinterpret_cast<uint4*>(smem + QLo + so) =
            *(reinterpret_cast<const uint4*>(qlp + (size_t)row * DH) + ch);
    }

    float mS[2][2], lS[2][2];
#pragma unroll
    for (int mt = 0; mt < 2; mt++) { mS[mt][0] = mS[mt][1] = -1e30f; lS[mt][0] = lS[mt][1] = 0.0f; }

    float o[2][8][4];
#pragma unroll
    for (int mt = 0; mt < 2; mt++)
#pragma unroll
        for (int nt = 0; nt < 8; nt++)
#pragma unroll
            for (int q = 0; q < 4; q++) o[mt][nt][q] = 0.0f;

    for (int kt64 = 0; kt64 < T_SEQ / 64; kt64++) {
        if (kt64 + 1 < T_SEQ / 64) { issue_kv(kt64 + 1, (kt64 + 1) & 1); CP_WAIT1(); }
        else                       { CP_WAIT0(); }
        __syncthreads();
        const char* bp = smem + 32768 + (kt64 & 1) * ATTN_KV_BUF;

        // ---- S2 = (Q*8*log2e) K^T (32 x 64 per warp), base-2 scores ----
        float s[2][8][4];
#pragma unroll
        for (int mt = 0; mt < 2; mt++)
#pragma unroll
            for (int nt = 0; nt < 8; nt++)
#pragma unroll
                for (int q = 0; q < 4; q++) s[mt][nt][q] = 0.0f;

#pragma unroll
        for (int kt = 0; kt < 4; kt++) {
            uint32_t qa[2][4], qb[2][4];
#pragma unroll
            for (int mt = 0; mt < 2; mt++) {
                const int row = wrow + mt * 16 + r;
                const uint32_t o0 = swz(row, kt * 32 + c4);
                const uint32_t o2 = swz(row, kt * 32 + c4 + 16);
                qa[mt][0] = *reinterpret_cast<const uint32_t*>(smem + QHo + o0);
                qa[mt][1] = *reinterpret_cast<const uint32_t*>(smem + QHo + o0 + 1024);
                qa[mt][2] = *reinterpret_cast<const uint32_t*>(smem + QHo + o2);
                qa[mt][3] = *reinterpret_cast<const uint32_t*>(smem + QHo + o2 + 1024);
                qb[mt][0] = *reinterpret_cast<const uint32_t*>(smem + QLo + o0);
                qb[mt][1] = *reinterpret_cast<const uint32_t*>(smem + QLo + o0 + 1024);
                qb[mt][2] = *reinterpret_cast<const uint32_t*>(smem + QLo + o2);
                qb[mt][3] = *reinterpret_cast<const uint32_t*>(smem + QLo + o2 + 1024);
            }
#pragma unroll
            for (int nt = 0; nt < 8; nt++) {
                const int rowb = nt * 8 + r;
                const uint32_t ob0 = swz(rowb, kt * 32 + c4);
                const uint32_t ob1 = swz(rowb, kt * 32 + c4 + 16);
                const uint32_t kh0 = *reinterpret_cast<const uint32_t*>(bp + KHo + ob0);
                const uint32_t kh1 = *reinterpret_cast<const uint32_t*>(bp + KHo + ob1);
                const uint32_t kl0 = *reinterpret_cast<const uint32_t*>(bp + KLo + ob0);
                const uint32_t kl1 = *reinterpret_cast<const uint32_t*>(bp + KLo + ob1);
                mma_f16(s[0][nt], qa[0], kh0, kh1);
                mma_f16(s[1][nt], qa[1], kh0, kh1);
                mma_f16(s[0][nt], qa[0], kl0, kl1);
                mma_f16(s[1][nt], qa[1], kl0, kl1);
                mma_f16(s[0][nt], qb[0], kh0, kh1);
                mma_f16(s[1][nt], qb[1], kh0, kh1);
            }
        }

        // ---- online softmax per mt (base-2; registers; quad shfl reduce) ----
        float alpha[2][2];
#pragma unroll
        for (int mt = 0; mt < 2; mt++) {
            float mx0 = -1e30f, mx1 = -1e30f;
#pragma unroll
            for (int nt = 0; nt < 8; nt++) {
                mx0 = fmaxf(mx0, fmaxf(s[mt][nt][0], s[mt][nt][1]));
                mx1 = fmaxf(mx1, fmaxf(s[mt][nt][2], s[mt][nt][3]));
            }
            mx0 = fmaxf(mx0, __shfl_xor_sync(0xffffffffu, mx0, 1));
            mx0 = fmaxf(mx0, __shfl_xor_sync(0xffffffffu, mx0, 2));
            mx1 = fmaxf(mx1, __shfl_xor_sync(0xffffffffu, mx1, 1));
            mx1 = fmaxf(mx1, __shfl_xor_sync(0xffffffffu, mx1, 2));

            const float mn0 = fmaxf(mS[mt][0], mx0);
            const float mn1 = fmaxf(mS[mt][1], mx1);
            alpha[mt][0] = ex2f(mS[mt][0] - mn0);
            alpha[mt][1] = ex2f(mS[mt][1] - mn1);
            mS[mt][0] = mn0; mS[mt][1] = mn1;

            float rs0 = 0.0f, rs1 = 0.0f;
#pragma unroll
            for (int nt = 0; nt < 8; nt++) {
                float p0 = ex2f(s[mt][nt][0] - mn0);
                float p1 = ex2f(s[mt][nt][1] - mn0);
                float p2 = ex2f(s[mt][nt][2] - mn1);
                float p3 = ex2f(s[mt][nt][3] - mn1);
                s[mt][nt][0] = p0; s[mt][nt][1] = p1; s[mt][nt][2] = p2; s[mt][nt][3] = p3;
                rs0 += p0 + p1;
                rs1 += p2 + p3;
            }
            rs0 += __shfl_xor_sync(0xffffffffu, rs0, 1);
            rs0 += __shfl_xor_sync(0xffffffffu, rs0, 2);
            rs1 += __shfl_xor_sync(0xffffffffu, rs1, 1);
            rs1 += __shfl_xor_sync(0xffffffffu, rs1, 2);
            lS[mt][0] = lS[mt][0] * alpha[mt][0] + rs0;
            lS[mt][1] = lS[mt][1] * alpha[mt][1] + rs1;

#pragma unroll
            for (int nt = 0; nt < 8; nt++) {
                o[mt][nt][0] *= alpha[mt][0]; o[mt][nt][1] *= alpha[mt][0];
                o[mt][nt][2] *= alpha[mt][1]; o[mt][nt][3] *= alpha[mt][1];
            }
        }

        // ---- O += P V ----
#pragma unroll
        for (int kt = 0; kt < 4; kt++) {
            uint32_t ph[2][4], pl[2][4];
#pragma unroll
            for (int mt = 0; mt < 2; mt++) {
                split2(s[mt][2 * kt][0],     s[mt][2 * kt][1],     ph[mt][0], pl[mt][0]);
                split2(s[mt][2 * kt][2],     s[mt][2 * kt][3],     ph[mt][1], pl[mt][1]);
                split2(s[mt][2 * kt + 1][0], s[mt][2 * kt + 1][1], ph[mt][2], pl[mt][2]);
                split2(s[mt][2 * kt + 1][2], s[mt][2 * kt + 1][3], ph[mt][3], pl[mt][3]);
            }
#pragma unroll
            for (int nt = 0; nt < 8; nt++) {
                const int rowv = nt * 8 + r;
                const uint32_t ov0 = swz(rowv, kt * 32 + c4);
                const uint32_t ov1 = swz(rowv, kt * 32 + c4 + 16);
                const uint32_t vh0 = *reinterpret_cast<const uint32_t*>(bp + VHo + ov0);
                const uint32_t vh1 = *reinterpret_cast<const uint32_t*>(bp + VHo + ov1);
                const uint32_t vl0 = *reinterpret_cast<const uint32_t*>(bp + VLo + ov0);
                const uint32_t vl1 = *reinterpret_cast<const uint32_t*>(bp + VLo + ov1);
                mma_f16(o[0][nt], ph[0], vh0, vh1);
                mma_f16(o[1][nt], ph[1], vh0, vh1);
                mma_f16(o[0][nt], ph[0], vl0, vl1);
                mma_f16(o[1][nt], ph[1], vl0, vl1);
                mma_f16(o[0][nt], pl[0], vh0, vh1);
                mma_f16(o[1][nt], pl[1], vh0, vh1);
            }
        }
        __syncthreads();
    }

    // Writeback -> g_oh/g_ol at [b][t][h*64+dh]
    const int b = bh / NH;
    const int h = bh - b * NH;
#pragma unroll
    for (int mt = 0; mt < 2; mt++) {
        const float li0 = 1.0f / lS[mt][0];
        const float li1 = 1.0f / lS[mt][1];
        const int t_r = t0 + wrow + mt * 16 + r;
#pragma unroll
        for (int nt = 0; nt < 8; nt++) {
            const int col = h * DH + nt * 8 + 2 * (lane & 3);
            uint32_t h0, l0, h1, l1;
            split2(o[mt][nt][0] * li0, o[mt][nt][1] * li0, h0, l0);
            split2(o[mt][nt][2] * li1, o[mt][nt][3] * li1, h1, l1);
            size_t p0 = ((size_t)b * T_SEQ + t_r) * DMODEL + col;
            size_t p1 = ((size_t)b * T_SEQ + t_r + 8) * DMODEL + col;
            *reinterpret_cast<uint32_t*>(g_oh + p0) = h0;
            *reinterpret_cast<uint32_t*>(g_ol + p0) = l0;
            *reinterpret_cast<uint32_t*>(g_oh + p1) = h1;
            *reinterpret_cast<uint32_t*>(g_ol + p1) = l1;
        }
    }
}

// ---------------------------------------------------------------------------
extern "C" void kernel_launch(void* const* d_in, const int* in_sizes, int n_in,
                              void* d_out, int out_size) {
    const float* x     = (const float*)d_in[0];   // [4, 2048, 768]
    const float* w_qkv = (const float*)d_in[1];   // [2304, 768]
    const float* w_out = (const float*)d_in[2];   // [768, 768]
    float* out = (float*)d_out;                   // [4, 2048, 768]

    constexpr int SMEM0 = 2 * (2 * 256 * 128 + 32768);   // 196608
    constexpr int SMEM1 = 2 * (2 * 128 * 128 + 32768);   // 131072

    cudaFuncSetAttribute((const void*)gemm_mma<0, 256, 256>,
                         cudaFuncAttributeMaxDynamicSharedMemorySize, SMEM0);
    cudaFuncSetAttribute((const void*)gemm_mma<1, 128, 128>,
                         cudaFuncAttributeMaxDynamicSharedMemorySize, SMEM1);
    cudaFuncSetAttribute((const void*)attn_mma,
                         cudaFuncAttributeMaxDynamicSharedMemorySize, ATTN_SMEM_BYTES);

    split_all<<<1024, 256>>>(x, w_qkv, w_out);
    gemm_mma<0, 256, 256><<<dim3(32, 18), 256, SMEM0>>>(nullptr);
    attn_mma<<<dim3(16, 48), 128, ATTN_SMEM_BYTES>>>();
    gemm_mma<1, 128, 128><<<dim3(64, 6), 128, SMEM1>>>(out);
}

// round 7
// speedup vs baseline: 4.1023x; 1.2928x over previous
#include <cuda_runtime.h>
#include <cuda_fp16.h>
#include <cstdint>

#define T_SEQ  2048
#define NB     4
#define NH     12
#define DH     64
#define DMODEL 768
#define BHN    (NB * NH)   // 48

// 8 * log2(e): softmax computed in base-2 domain
#define QSCALE 11.5415603f

// ---------------------------------------------------------------------------
// Device-global scratch. fp16 hi/lo splits (lo only where 3-term is needed).
// ---------------------------------------------------------------------------
__device__ uint16_t g_xh[(size_t)NB * T_SEQ * DMODEL];
__device__ uint16_t g_xl[(size_t)NB * T_SEQ * DMODEL];
__device__ uint16_t g_wqh[(size_t)3 * DMODEL * DMODEL];
__device__ uint16_t g_wql[(size_t)3 * DMODEL * DMODEL];
__device__ uint16_t g_woh[(size_t)DMODEL * DMODEL];
__device__ uint16_t g_wol[(size_t)DMODEL * DMODEL];

__device__ uint16_t g_qh[(size_t)BHN * T_SEQ * DH];   // Q pre-scaled by 8*log2(e)
__device__ uint16_t g_ql[(size_t)BHN * T_SEQ * DH];
__device__ uint16_t g_kh[(size_t)BHN * T_SEQ * DH];
__device__ uint16_t g_kl[(size_t)BHN * T_SEQ * DH];
__device__ uint16_t g_vth[(size_t)BHN * DH * T_SEQ];  // V^T: [bh][dh][t] (hi only)

__device__ uint16_t g_oh[(size_t)NB * T_SEQ * DMODEL]; // attention out (hi only)

// ---------------------------------------------------------------------------
// Helpers
// ---------------------------------------------------------------------------
__device__ __forceinline__ uint32_t smem_u32(const void* p) {
    uint32_t a;
    asm("{ .reg .u64 t; cvta.to.shared.u64 t, %1; cvt.u32.u64 %0, t; }"
        : "=r"(a) : "l"(p));
    return a;
}

__device__ __forceinline__ float ex2f(float x) {
    float y;
    asm("ex2.approx.f32 %0, %1;" : "=f"(y) : "f"(x));
    return y;
}

__device__ __forceinline__ uint32_t packh2(float x0, float x1) {
    __half2 hh = __floats2half2_rn(x0, x1);
    return *reinterpret_cast<uint32_t*>(&hh);
}

__device__ __forceinline__ void split2(float x0, float x1, uint32_t& h, uint32_t& l) {
    __half2 hh = __floats2half2_rn(x0, x1);
    __half2 ll = __floats2half2_rn(x0 - __low2float(hh), x1 - __high2float(hh));
    h = *reinterpret_cast<uint32_t*>(&hh);
    l = *reinterpret_cast<uint32_t*>(&ll);
}

// m16n8k16 fp16 mma, fp32 accum. A row-major, B col-major.
__device__ __forceinline__ void mma_f16(float* d, const uint32_t* a, uint32_t b0, uint32_t b1) {
    asm volatile(
        "mma.sync.aligned.m16n8k16.row.col.f32.f16.f16.f32 "
        "{%0,%1,%2,%3}, {%4,%5,%6,%7}, {%8,%9}, {%0,%1,%2,%3};"
        : "+f"(d[0]), "+f"(d[1]), "+f"(d[2]), "+f"(d[3])
        : "r"(a[0]), "r"(a[1]), "r"(a[2]), "r"(a[3]), "r"(b0), "r"(b1));
}

// Swizzled smem byte offset within a tile of 128B rows
__device__ __forceinline__ uint32_t swz(int row, int byteoff) {
    return (uint32_t)(row * 128 + (byteoff ^ ((row & 7) << 4)));
}

#define CP_ASYNC16(dst_u32, src_ptr) \
    asm volatile("cp.async.cg.shared.global [%0], [%1], 16;" \
                 :: "r"(dst_u32), "l"(src_ptr) : "memory")
#define CP_COMMIT() asm volatile("cp.async.commit_group;" ::: "memory")
#define CP_WAIT1()  asm volatile("cp.async.wait_group 1;" ::: "memory")
#define CP_WAIT0()  asm volatile("cp.async.wait_group 0;" ::: "memory")

// ---------------------------------------------------------------------------
// Split fp32 -> fp16 (hi, lo)
// ---------------------------------------------------------------------------
__global__ void split_all(const float* __restrict__ x, const float* __restrict__ wq,
                          const float* __restrict__ wo) {
    const int N1 = (NB * T_SEQ * DMODEL) / 4;
    const int N2 = (3 * DMODEL * DMODEL) / 4;
    const int N3 = (DMODEL * DMODEL) / 4;
    const int tot = N1 + N2 + N3;
    for (int i = blockIdx.x * blockDim.x + threadIdx.x; i < tot; i += gridDim.x * blockDim.x) {
        const float4* src;
        uint16_t *dh, *dl;
        int j;
        if (i < N1)           { src = (const float4*)x;  j = i;           dh = g_xh;  dl = g_xl; }
        else if (i < N1 + N2) { src = (const float4*)wq; j = i - N1;      dh = g_wqh; dl = g_wql; }
        else                  { src = (const float4*)wo; j = i - N1 - N2; dh = g_woh; dl = g_wol; }
        float4 v = src[j];
        uint32_t h0, l0, h1, l1;
        split2(v.x, v.y, h0, l0);
        split2(v.z, v.w, h1, l1);
        *reinterpret_cast<uint2*>(dh + 4 * (size_t)j) = uint2{h0, h1};
        *reinterpret_cast<uint2*>(dl + 4 * (size_t)j) = uint2{l0, l1};
    }
}

// ---------------------------------------------------------------------------
// mma.sync split-fp16 GEMM, cp.async double-buffered.
// MODE 0 (QKV): CTAM=256, 256 thr, warp tile 64x64 (MT=4).
//               by<12 (Q,K cols): 3-term.  by>=12 (V cols): 1-term.
// MODE 1 (out): CTAM=128, 256 thr, warp tile 32x64 (MT=2). 2-term (Ah only).
// ---------------------------------------------------------------------------
template <int MODE, int CTAM, int NTHR>
__global__ void __launch_bounds__(NTHR, 1) gemm_mma(float* __restrict__ C) {
    extern __shared__ char smem[];
    const uint32_t sb = smem_u32(smem);
    constexpr int MT = (MODE == 0) ? 4 : 2;
    constexpr int ABYTES = CTAM * 128;
    constexpr int AHo = 0, ALo = ABYTES, BHo = 2 * ABYTES, BLo = 2 * ABYTES + 16384;
    constexpr int STAGE = 2 * ABYTES + 32768;

    const int tid = threadIdx.x;
    const int lane = tid & 31;
    const int wid = tid >> 5;
    const int r = lane >> 2;
    const int c4 = (lane & 3) * 4;
    const int m0 = blockIdx.x * CTAM;
    const int by = blockIdx.y;
    const int wm = (wid >> 1) * (16 * MT);
    const int wn = (wid & 1) * 64;

    const bool t3 = (MODE == 0) && (by < 12);       // 3-term (Q,K columns)
    const bool useBL = (MODE == 1) || t3;

    const uint16_t* Ah = (MODE == 0) ? g_xh : g_oh;
    const uint16_t* Al = g_xl;                      // only used when t3
    const uint16_t* Bh = (MODE == 0) ? g_wqh : g_woh;
    const uint16_t* Bl = (MODE == 0) ? g_wql : g_wol;

    auto issue_stage = [&](int c, int buf) {
        const int k0 = c * 64;
        const uint32_t base = sb + buf * STAGE;
#pragma unroll
        for (int it = 0; it < CTAM * 8 / NTHR; it++) {
            const int idx = it * NTHR + tid;
            const int row = idx >> 3;
            const int ch = idx & 7;
            const uint32_t so = swz(row, ch * 16);
            CP_ASYNC16(base + AHo + so, Ah + (size_t)(m0 + row) * DMODEL + k0 + ch * 8);
            if (t3)
                CP_ASYNC16(base + ALo + so, Al + (size_t)(m0 + row) * DMODEL + k0 + ch * 8);
        }
#pragma unroll
        for (int it = 0; it < 1024 / NTHR; it++) {
            const int idx = it * NTHR + tid;
            const int row = idx >> 3;
            const int ch = idx & 7;
            const uint32_t so = swz(row, ch * 16);
            const int grow = (MODE == 0) ? ((row & 63) * 36 + by * 2 + (row >> 6))
                                         : (by * 128 + row);
            CP_ASYNC16(base + BHo + so, Bh + (size_t)grow * DMODEL + k0 + ch * 8);
            if (useBL)
                CP_ASYNC16(base + BLo + so, Bl + (size_t)grow * DMODEL + k0 + ch * 8);
        }
        CP_COMMIT();
    };

    float acc[MT][8][4];
#pragma unroll
    for (int mt = 0; mt < MT; mt++)
#pragma unroll
        for (int nt = 0; nt < 8; nt++)
#pragma unroll
            for (int q = 0; q < 4; q++) acc[mt][nt][q] = 0.0f;

    issue_stage(0, 0);

    for (int c = 0; c < 12; c++) {
        if (c + 1 < 12) { issue_stage(c + 1, (c + 1) & 1); CP_WAIT1(); }
        else            { CP_WAIT0(); }
        __syncthreads();
        const char* bp = smem + (c & 1) * STAGE;

#pragma unroll
        for (int kt = 0; kt < 4; kt++) {
            uint32_t aH[MT][4], aL[MT][4];
#pragma unroll
            for (int mt = 0; mt < MT; mt++) {
                const int row = wm + mt * 16 + r;
                const uint32_t o0 = swz(row, kt * 32 + c4);
                const uint32_t o2 = swz(row, kt * 32 + c4 + 16);
                aH[mt][0] = *reinterpret_cast<const uint32_t*>(bp + AHo + o0);
                aH[mt][1] = *reinterpret_cast<const uint32_t*>(bp + AHo + o0 + 1024);
                aH[mt][2] = *reinterpret_cast<const uint32_t*>(bp + AHo + o2);
                aH[mt][3] = *reinterpret_cast<const uint32_t*>(bp + AHo + o2 + 1024);
                if (t3) {
                    aL[mt][0] = *reinterpret_cast<const uint32_t*>(bp + ALo + o0);
                    aL[mt][1] = *reinterpret_cast<const uint32_t*>(bp + ALo + o0 + 1024);
                    aL[mt][2] = *reinterpret_cast<const uint32_t*>(bp + ALo + o2);
                    aL[mt][3] = *reinterpret_cast<const uint32_t*>(bp + ALo + o2 + 1024);
                }
            }
#pragma unroll
            for (int nt = 0; nt < 8; nt++) {
                const int rowb = wn + nt * 8 + r;
                const uint32_t ob0 = swz(rowb, kt * 32 + c4);
                const uint32_t ob1 = swz(rowb, kt * 32 + c4 + 16);
                const uint32_t bh0 = *reinterpret_cast<const uint32_t*>(bp + BHo + ob0);
                const uint32_t bh1 = *reinterpret_cast<const uint32_t*>(bp + BHo + ob1);
#pragma unroll
                for (int mt = 0; mt < MT; mt++) mma_f16(acc[mt][nt], aH[mt], bh0, bh1);
                if (useBL) {
                    const uint32_t bl0 = *reinterpret_cast<const uint32_t*>(bp + BLo + ob0);
                    const uint32_t bl1 = *reinterpret_cast<const uint32_t*>(bp + BLo + ob1);
#pragma unroll
                    for (int mt = 0; mt < MT; mt++) mma_f16(acc[mt][nt], aH[mt], bl0, bl1);
                }
                if (t3) {
                    const uint32_t bh0c = bh0, bh1c = bh1;
#pragma unroll
                    for (int mt = 0; mt < MT; mt++) mma_f16(acc[mt][nt], aL[mt], bh0c, bh1c);
                }
            }
        }
        __syncthreads();
    }

    // Epilogue
#pragma unroll
    for (int mt = 0; mt < MT; mt++) {
        const int mrow = m0 + wm + mt * 16 + r;
#pragma unroll
        for (int nt = 0; nt < 8; nt++) {
            const int nl = wn + nt * 8 + 2 * (lane & 3);
            float d0 = acc[mt][nt][0], d1 = acc[mt][nt][1];
            float d2 = acc[mt][nt][2], d3 = acc[mt][nt][3];
            if (MODE == 0) {
                const int koff = by * 2 + (nl >> 6);
                const int dh = nl & 63;
                const int k3 = koff / 12;
                const int h = koff - 12 * k3;
                const int b = mrow >> 11;
                const int t = mrow & 2047;
                const int bhI = b * NH + h;
                if (k3 == 0) { d0 *= QSCALE; d1 *= QSCALE; d2 *= QSCALE; d3 *= QSCALE; }
                if (k3 == 2) {
                    // V: hi only, transposed layout
                    uint32_t h0 = packh2(d0, d1), h1 = packh2(d2, d3);
                    size_t q0 = ((size_t)bhI * DH + dh) * T_SEQ + t;
                    size_t q1 = ((size_t)bhI * DH + dh + 1) * T_SEQ + t;
                    g_vth[q0] = (uint16_t)h0;      g_vth[q1] = (uint16_t)(h0 >> 16);
                    g_vth[q0 + 8] = (uint16_t)h1;  g_vth[q1 + 8] = (uint16_t)(h1 >> 16);
                } else {
                    uint32_t h0, l0, h1, l1;
                    split2(d0, d1, h0, l0);
                    split2(d2, d3, h1, l1);
                    uint16_t* dsth = (k3 == 0) ? g_qh : g_kh;
                    uint16_t* dstl = (k3 == 0) ? g_ql : g_kl;
                    size_t p0 = ((size_t)bhI * T_SEQ + t) * DH + dh;
                    size_t p1 = ((size_t)bhI * T_SEQ + t + 8) * DH + dh;
                    *reinterpret_cast<uint32_t*>(dsth + p0) = h0;
                    *reinterpret_cast<uint32_t*>(dstl + p0) = l0;
                    *reinterpret_cast<uint32_t*>(dsth + p1) = h1;
                    *reinterpret_cast<uint32_t*>(dstl + p1) = l1;
                }
            } else {
                float2 p0{d0, d1}, p1{d2, d3};
                *reinterpret_cast<float2*>(C + (size_t)mrow * DMODEL + by * 128 + nl) = p0;
                *reinterpret_cast<float2*>(C + (size_t)(mrow + 8) * DMODEL + by * 128 + nl) = p1;
            }
        }
    }
}

// ---------------------------------------------------------------------------
// Flash attention: 128 threads (4 warps), warp tile 32 q-rows x 64 keys.
// QK^T 3-term, PV single-term. Base-2 softmax. cp.async double-buffered KV.
// ---------------------------------------------------------------------------
#define ATTN_KV_BUF   24576
#define ATTN_SMEM_BYTES (32768 + 2 * ATTN_KV_BUF)   // Q(32K) + 2 KV stages (24K each)

__global__ void __launch_bounds__(128) attn_mma() {
    extern __shared__ char smem[];
    const uint32_t sb = smem_u32(smem);
    const int QHo = 0, QLo = 16384;
    const int KHo = 0, KLo = 8192, VHo = 16384;     // within KV stage

    const int tid = threadIdx.x;
    const int lane = tid & 31;
    const int wid = tid >> 5;          // 0..3
    const int r = lane >> 2;
    const int c4 = (lane & 3) * 4;
    const int bh = blockIdx.y;
    const int t0 = blockIdx.x * 128;
    const int wrow = wid * 32;

    const uint16_t* kh = g_kh + (size_t)bh * T_SEQ * DH;
    const uint16_t* kl = g_kl + (size_t)bh * T_SEQ * DH;
    const uint16_t* vh = g_vth + (size_t)bh * DH * T_SEQ;

    auto issue_kv = [&](int kt, int buf) {
        const uint32_t base = sb + 32768 + buf * ATTN_KV_BUF;
#pragma unroll
        for (int it = 0; it < 4; it++) {
            const int idx = it * 128 + tid;
            const int row = idx >> 3;
            const int ch = idx & 7;
            const uint32_t so = swz(row, ch * 16);
            CP_ASYNC16(base + KHo + so, kh + (size_t)(kt * 64 + row) * DH + ch * 8);
            CP_ASYNC16(base + KLo + so, kl + (size_t)(kt * 64 + row) * DH + ch * 8);
            CP_ASYNC16(base + VHo + so, vh + (size_t)row * T_SEQ + kt * 64 + ch * 8);
        }
        CP_COMMIT();
    };

    issue_kv(0, 0);

    const uint16_t* qhp = g_qh + ((size_t)bh * T_SEQ + t0) * DH;
    const uint16_t* qlp = g_ql + ((size_t)bh * T_SEQ + t0) * DH;
#pragma unroll
    for (int it = 0; it < 8; it++) {
        const int idx = it * 128 + tid;
        const int row = idx >> 3;
        const int ch = idx & 7;
        const uint32_t so = swz(row, ch * 16);
        *reinterpret_cast<uint4*>(smem + QHo + so) =
            *(reinterpret_cast<const uint4*>(qhp + (size_t)row * DH) + ch);
        *reinterpret_cast<uint4*>(smem + QLo + so) =
            *(reinterpret_cast<const uint4*>(qlp + (size_t)row * DH) + ch);
    }

    float mS[2][2], lS[2][2];
#pragma unroll
    for (int mt = 0; mt < 2; mt++) { mS[mt][0] = mS[mt][1] = -1e30f; lS[mt][0] = lS[mt][1] = 0.0f; }

    float o[2][8][4];
#pragma unroll
    for (int mt = 0; mt < 2; mt++)
#pragma unroll
        for (int nt = 0; nt < 8; nt++)
#pragma unroll
            for (int q = 0; q < 4; q++) o[mt][nt][q] = 0.0f;

    for (int kt64 = 0; kt64 < T_SEQ / 64; kt64++) {
        if (kt64 + 1 < T_SEQ / 64) { issue_kv(kt64 + 1, (kt64 + 1) & 1); CP_WAIT1(); }
        else                       { CP_WAIT0(); }
        __syncthreads();
        const char* bp = smem + 32768 + (kt64 & 1) * ATTN_KV_BUF;

        // ---- S2 = (Q*8*log2e) K^T, 3-term ----
        float s[2][8][4];
#pragma unroll
        for (int mt = 0; mt < 2; mt++)
#pragma unroll
            for (int nt = 0; nt < 8; nt++)
#pragma unroll
                for (int q = 0; q < 4; q++) s[mt][nt][q] = 0.0f;

#pragma unroll
        for (int kt = 0; kt < 4; kt++) {
            uint32_t qa[2][4], qb[2][4];
#pragma unroll
            for (int mt = 0; mt < 2; mt++) {
                const int row = wrow + mt * 16 + r;
                const uint32_t o0 = swz(row, kt * 32 + c4);
                const uint32_t o2 = swz(row, kt * 32 + c4 + 16);
                qa[mt][0] = *reinterpret_cast<const uint32_t*>(smem + QHo + o0);
                qa[mt][1] = *reinterpret_cast<const uint32_t*>(smem + QHo + o0 + 1024);
                qa[mt][2] = *reinterpret_cast<const uint32_t*>(smem + QHo + o2);
                qa[mt][3] = *reinterpret_cast<const uint32_t*>(smem + QHo + o2 + 1024);
                qb[mt][0] = *reinterpret_cast<const uint32_t*>(smem + QLo + o0);
                qb[mt][1] = *reinterpret_cast<const uint32_t*>(smem + QLo + o0 + 1024);
                qb[mt][2] = *reinterpret_cast<const uint32_t*>(smem + QLo + o2);
                qb[mt][3] = *reinterpret_cast<const uint32_t*>(smem + QLo + o2 + 1024);
            }
#pragma unroll
            for (int nt = 0; nt < 8; nt++) {
                const int rowb = nt * 8 + r;
                const uint32_t ob0 = swz(rowb, kt * 32 + c4);
                const uint32_t ob1 = swz(rowb, kt * 32 + c4 + 16);
                const uint32_t kh0 = *reinterpret_cast<const uint32_t*>(bp + KHo + ob0);
                const uint32_t kh1 = *reinterpret_cast<const uint32_t*>(bp + KHo + ob1);
                const uint32_t kl0 = *reinterpret_cast<const uint32_t*>(bp + KLo + ob0);
                const uint32_t kl1 = *reinterpret_cast<const uint32_t*>(bp + KLo + ob1);
                mma_f16(s[0][nt], qa[0], kh0, kh1);
                mma_f16(s[1][nt], qa[1], kh0, kh1);
                mma_f16(s[0][nt], qa[0], kl0, kl1);
                mma_f16(s[1][nt], qa[1], kl0, kl1);
                mma_f16(s[0][nt], qb[0], kh0, kh1);
                mma_f16(s[1][nt], qb[1], kh0, kh1);
            }
        }

        // ---- online softmax (base-2; registers; quad shfl reduce) ----
        float alpha[2][2];
#pragma unroll
        for (int mt = 0; mt < 2; mt++) {
            float mx0 = -1e30f, mx1 = -1e30f;
#pragma unroll
            for (int nt = 0; nt < 8; nt++) {
                mx0 = fmaxf(mx0, fmaxf(s[mt][nt][0], s[mt][nt][1]));
                mx1 = fmaxf(mx1, fmaxf(s[mt][nt][2], s[mt][nt][3]));
            }
            mx0 = fmaxf(mx0, __shfl_xor_sync(0xffffffffu, mx0, 1));
            mx0 = fmaxf(mx0, __shfl_xor_sync(0xffffffffu, mx0, 2));
            mx1 = fmaxf(mx1, __shfl_xor_sync(0xffffffffu, mx1, 1));
            mx1 = fmaxf(mx1, __shfl_xor_sync(0xffffffffu, mx1, 2));

            const float mn0 = fmaxf(mS[mt][0], mx0);
            const float mn1 = fmaxf(mS[mt][1], mx1);
            alpha[mt][0] = ex2f(mS[mt][0] - mn0);
            alpha[mt][1] = ex2f(mS[mt][1] - mn1);
            mS[mt][0] = mn0; mS[mt][1] = mn1;

            float rs0 = 0.0f, rs1 = 0.0f;
#pragma unroll
            for (int nt = 0; nt < 8; nt++) {
                float p0 = ex2f(s[mt][nt][0] - mn0);
                float p1 = ex2f(s[mt][nt][1] - mn0);
                float p2 = ex2f(s[mt][nt][2] - mn1);
                float p3 = ex2f(s[mt][nt][3] - mn1);
                s[mt][nt][0] = p0; s[mt][nt][1] = p1; s[mt][nt][2] = p2; s[mt][nt][3] = p3;
                rs0 += p0 + p1;
                rs1 += p2 + p3;
            }
            rs0 += __shfl_xor_sync(0xffffffffu, rs0, 1);
            rs0 += __shfl_xor_sync(0xffffffffu, rs0, 2);
            rs1 += __shfl_xor_sync(0xffffffffu, rs1, 1);
            rs1 += __shfl_xor_sync(0xffffffffu, rs1, 2);
            lS[mt][0] = lS[mt][0] * alpha[mt][0] + rs0;
            lS[mt][1] = lS[mt][1] * alpha[mt][1] + rs1;

#pragma unroll
            for (int nt = 0; nt < 8; nt++) {
                o[mt][nt][0] *= alpha[mt][0]; o[mt][nt][1] *= alpha[mt][0];
                o[mt][nt][2] *= alpha[mt][1]; o[mt][nt][3] *= alpha[mt][1];
            }
        }

        // ---- O += P V : single-term (P hi only) ----
#pragma unroll
        for (int kt = 0; kt < 4; kt++) {
            uint32_t ph[2][4];
#pragma unroll
            for (int mt = 0; mt < 2; mt++) {
                ph[mt][0] = packh2(s[mt][2 * kt][0],     s[mt][2 * kt][1]);
                ph[mt][1] = packh2(s[mt][2 * kt][2],     s[mt][2 * kt][3]);
                ph[mt][2] = packh2(s[mt][2 * kt + 1][0], s[mt][2 * kt + 1][1]);
                ph[mt][3] = packh2(s[mt][2 * kt + 1][2], s[mt][2 * kt + 1][3]);
            }
#pragma unroll
            for (int nt = 0; nt < 8; nt++) {
                const int rowv = nt * 8 + r;
                const uint32_t ov0 = swz(rowv, kt * 32 + c4);
                const uint32_t ov1 = swz(rowv, kt * 32 + c4 + 16);
                const uint32_t vh0 = *reinterpret_cast<const uint32_t*>(bp + VHo + ov0);
                const uint32_t vh1 = *reinterpret_cast<const uint32_t*>(bp + VHo + ov1);
                mma_f16(o[0][nt], ph[0], vh0, vh1);
                mma_f16(o[1][nt], ph[1], vh0, vh1);
            }
        }
        __syncthreads();
    }

    // Writeback -> g_oh only
    const int b = bh / NH;
    const int h = bh - b * NH;
#pragma unroll
    for (int mt = 0; mt < 2; mt++) {
        const float li0 = 1.0f / lS[mt][0];
        const float li1 = 1.0f / lS[mt][1];
        const int t_r = t0 + wrow + mt * 16 + r;
#pragma unroll
        for (int nt = 0; nt < 8; nt++) {
            const int col = h * DH + nt * 8 + 2 * (lane & 3);
            uint32_t h0 = packh2(o[mt][nt][0] * li0, o[mt][nt][1] * li0);
            uint32_t h1 = packh2(o[mt][nt][2] * li1, o[mt][nt][3] * li1);
            size_t p0 = ((size_t)b * T_SEQ + t_r) * DMODEL + col;
            size_t p1 = ((size_t)b * T_SEQ + t_r + 8) * DMODEL + col;
            *reinterpret_cast<uint32_t*>(g_oh + p0) = h0;
            *reinterpret_cast<uint32_t*>(g_oh + p1) = h1;
        }
    }
}

// ---------------------------------------------------------------------------
extern "C" void kernel_launch(void* const* d_in, const int* in_sizes, int n_in,
                              void* d_out, int out_size) {
    const float* x     = (const float*)d_in[0];   // [4, 2048, 768]
    const float* w_qkv = (const float*)d_in[1];   // [2304, 768]
    const float* w_out = (const float*)d_in[2];   // [768, 768]
    float* out = (float*)d_out;                   // [4, 2048, 768]

    constexpr int SMEM0 = 2 * (2 * 256 * 128 + 32768);   // 196608
    constexpr int SMEM1 = 2 * (2 * 128 * 128 + 32768);   // 131072

    cudaFuncSetAttribute((const void*)gemm_mma<0, 256, 256>,
                         cudaFuncAttributeMaxDynamicSharedMemorySize, SMEM0);
    cudaFuncSetAttribute((const void*)gemm_mma<1, 128, 256>,
                         cudaFuncAttributeMaxDynamicSharedMemorySize, SMEM1);
    cudaFuncSetAttribute((const void*)attn_mma,
                         cudaFuncAttributeMaxDynamicSharedMemorySize, ATTN_SMEM_BYTES);

    split_all<<<1024, 256>>>(x, w_qkv, w_out);
    gemm_mma<0, 256, 256><<<dim3(32, 18), 256, SMEM0>>>(nullptr);
    attn_mma<<<dim3(16, 48), 128, ATTN_SMEM_BYTES>>>();
    gemm_mma<1, 128, 256><<<dim3(64, 6), 256, SMEM1>>>(out);
}

// round 8
// speedup vs baseline: 4.4925x; 1.0951x over previous
#include <cuda_runtime.h>
#include <cuda_fp16.h>
#include <cstdint>

#define T_SEQ  2048
#define NB     4
#define NH     12
#define DH     64
#define DMODEL 768
#define BHN    (NB * NH)   // 48

// 8 * log2(e): softmax computed in base-2 domain
#define QSCALE 11.5415603f

// ---------------------------------------------------------------------------
// Device-global scratch. fp16 hi/lo splits (lo only where 3-term is needed).
// ---------------------------------------------------------------------------
__device__ uint16_t g_xh[(size_t)NB * T_SEQ * DMODEL];
__device__ uint16_t g_xl[(size_t)NB * T_SEQ * DMODEL];
__device__ uint16_t g_wqh[(size_t)3 * DMODEL * DMODEL];
__device__ uint16_t g_wql[(size_t)3 * DMODEL * DMODEL];
__device__ uint16_t g_woh[(size_t)DMODEL * DMODEL];
__device__ uint16_t g_wol[(size_t)DMODEL * DMODEL];

__device__ uint16_t g_qh[(size_t)BHN * T_SEQ * DH];   // Q pre-scaled by 8*log2(e)
__device__ uint16_t g_ql[(size_t)BHN * T_SEQ * DH];
__device__ uint16_t g_kh[(size_t)BHN * T_SEQ * DH];
__device__ uint16_t g_kl[(size_t)BHN * T_SEQ * DH];
__device__ uint16_t g_vth[(size_t)BHN * DH * T_SEQ];  // V^T: [bh][dh][t] (hi only)

__device__ uint16_t g_oh[(size_t)NB * T_SEQ * DMODEL]; // attention out (hi only)

// ---------------------------------------------------------------------------
// Helpers
// ---------------------------------------------------------------------------
__device__ __forceinline__ uint32_t smem_u32(const void* p) {
    uint32_t a;
    asm("{ .reg .u64 t; cvta.to.shared.u64 t, %1; cvt.u32.u64 %0, t; }"
        : "=r"(a) : "l"(p));
    return a;
}

__device__ __forceinline__ float ex2f(float x) {
    float y;
    asm("ex2.approx.f32 %0, %1;" : "=f"(y) : "f"(x));
    return y;
}

__device__ __forceinline__ uint32_t packh2(float x0, float x1) {
    __half2 hh = __floats2half2_rn(x0, x1);
    return *reinterpret_cast<uint32_t*>(&hh);
}

__device__ __forceinline__ void split2(float x0, float x1, uint32_t& h, uint32_t& l) {
    __half2 hh = __floats2half2_rn(x0, x1);
    __half2 ll = __floats2half2_rn(x0 - __low2float(hh), x1 - __high2float(hh));
    h = *reinterpret_cast<uint32_t*>(&hh);
    l = *reinterpret_cast<uint32_t*>(&ll);
}

// m16n8k16 fp16 mma, fp32 accum. A row-major, B col-major.
__device__ __forceinline__ void mma_f16(float* d, const uint32_t* a, uint32_t b0, uint32_t b1) {
    asm volatile(
        "mma.sync.aligned.m16n8k16.row.col.f32.f16.f16.f32 "
        "{%0,%1,%2,%3}, {%4,%5,%6,%7}, {%8,%9}, {%0,%1,%2,%3};"
        : "+f"(d[0]), "+f"(d[1]), "+f"(d[2]), "+f"(d[3])
        : "r"(a[0]), "r"(a[1]), "r"(a[2]), "r"(a[3]), "r"(b0), "r"(b1));
}

// ldmatrix x4: loads 4 8x8 b16 matrices; lane i supplies row address of matrix i/8.
__device__ __forceinline__ void ldsm4(uint32_t* r, uint32_t addr) {
    asm volatile("ldmatrix.sync.aligned.m8n8.x4.shared.b16 {%0,%1,%2,%3}, [%4];"
                 : "=r"(r[0]), "=r"(r[1]), "=r"(r[2]), "=r"(r[3]) : "r"(addr));
}

// Swizzled smem byte offset within a tile of 128B rows
__device__ __forceinline__ uint32_t swz(int row, int byteoff) {
    return (uint32_t)(row * 128 + (byteoff ^ ((row & 7) << 4)));
}

#define CP_ASYNC16(dst_u32, src_ptr) \
    asm volatile("cp.async.cg.shared.global [%0], [%1], 16;" \
                 :: "r"(dst_u32), "l"(src_ptr) : "memory")
#define CP_COMMIT() asm volatile("cp.async.commit_group;" ::: "memory")
#define CP_WAIT1()  asm volatile("cp.async.wait_group 1;" ::: "memory")
#define CP_WAIT0()  asm volatile("cp.async.wait_group 0;" ::: "memory")

// ---------------------------------------------------------------------------
// Split fp32 -> fp16 (hi, lo)
// ---------------------------------------------------------------------------
__global__ void split_all(const float* __restrict__ x, const float* __restrict__ wq,
                          const float* __restrict__ wo) {
    const int N1 = (NB * T_SEQ * DMODEL) / 4;
    const int N2 = (3 * DMODEL * DMODEL) / 4;
    const int N3 = (DMODEL * DMODEL) / 4;
    const int tot = N1 + N2 + N3;
    for (int i = blockIdx.x * blockDim.x + threadIdx.x; i < tot; i += gridDim.x * blockDim.x) {
        const float4* src;
        uint16_t *dh, *dl;
        int j;
        if (i < N1)           { src = (const float4*)x;  j = i;           dh = g_xh;  dl = g_xl; }
        else if (i < N1 + N2) { src = (const float4*)wq; j = i - N1;      dh = g_wqh; dl = g_wql; }
        else                  { src = (const float4*)wo; j = i - N1 - N2; dh = g_woh; dl = g_wol; }
        float4 v = src[j];
        uint32_t h0, l0, h1, l1;
        split2(v.x, v.y, h0, l0);
        split2(v.z, v.w, h1, l1);
        *reinterpret_cast<uint2*>(dh + 4 * (size_t)j) = uint2{h0, h1};
        *reinterpret_cast<uint2*>(dl + 4 * (size_t)j) = uint2{l0, l1};
    }
}

// ---------------------------------------------------------------------------
// mma.sync split-fp16 GEMM, cp.async double-buffered, ldmatrix fragments.
// MODE 0 (QKV): CTAM=256, 256 thr, warp tile 64x64 (MT=4).
//               by<12 (Q,K cols): 3-term.  by>=12 (V cols): 1-term.
// MODE 1 (out): CTAM=128, 256 thr, warp tile 32x64 (MT=2). 2-term.
// ---------------------------------------------------------------------------
template <int MODE, int CTAM, int NTHR>
__global__ void __launch_bounds__(NTHR, 1) gemm_mma(float* __restrict__ C) {
    extern __shared__ char smem[];
    const uint32_t sb = smem_u32(smem);
    constexpr int MT = (MODE == 0) ? 4 : 2;
    constexpr int ABYTES = CTAM * 128;
    constexpr int AHo = 0, ALo = ABYTES, BHo = 2 * ABYTES, BLo = 2 * ABYTES + 16384;
    constexpr int STAGE = 2 * ABYTES + 32768;

    const int tid = threadIdx.x;
    const int lane = tid & 31;
    const int wid = tid >> 5;
    const int m0 = blockIdx.x * CTAM;
    const int by = blockIdx.y;
    const int wm = (wid >> 1) * (16 * MT);
    const int wn = (wid & 1) * 64;

    // ldmatrix lane-address components
    const int laA = lane & 15;                 // A: row offset within 16
    const int lbA = (lane >> 4) * 16;          // A: k-half byte offset
    const int laB = (lane >> 4) * 8 + (lane & 7);   // B: row offset within 16
    const int lbB = ((lane >> 3) & 1) * 16;    // B: k-half byte offset

    const bool t3 = (MODE == 0) && (by < 12);
    const bool useBL = (MODE == 1) || t3;

    const uint16_t* Ah = (MODE == 0) ? g_xh : g_oh;
    const uint16_t* Al = g_xl;
    const uint16_t* Bh = (MODE == 0) ? g_wqh : g_woh;
    const uint16_t* Bl = (MODE == 0) ? g_wql : g_wol;

    auto issue_stage = [&](int c, int buf) {
        const int k0 = c * 64;
        const uint32_t base = sb + buf * STAGE;
#pragma unroll
        for (int it = 0; it < CTAM * 8 / NTHR; it++) {
            const int idx = it * NTHR + tid;
            const int row = idx >> 3;
            const int ch = idx & 7;
            const uint32_t so = swz(row, ch * 16);
            CP_ASYNC16(base + AHo + so, Ah + (size_t)(m0 + row) * DMODEL + k0 + ch * 8);
            if (t3)
                CP_ASYNC16(base + ALo + so, Al + (size_t)(m0 + row) * DMODEL + k0 + ch * 8);
        }
#pragma unroll
        for (int it = 0; it < 1024 / NTHR; it++) {
            const int idx = it * NTHR + tid;
            const int row = idx >> 3;
            const int ch = idx & 7;
            const uint32_t so = swz(row, ch * 16);
            const int grow = (MODE == 0) ? ((row & 63) * 36 + by * 2 + (row >> 6))
                                         : (by * 128 + row);
            CP_ASYNC16(base + BHo + so, Bh + (size_t)grow * DMODEL + k0 + ch * 8);
            if (useBL)
                CP_ASYNC16(base + BLo + so, Bl + (size_t)grow * DMODEL + k0 + ch * 8);
        }
        CP_COMMIT();
    };

    float acc[MT][8][4];
#pragma unroll
    for (int mt = 0; mt < MT; mt++)
#pragma unroll
        for (int nt = 0; nt < 8; nt++)
#pragma unroll
            for (int q = 0; q < 4; q++) acc[mt][nt][q] = 0.0f;

    issue_stage(0, 0);

    for (int c = 0; c < 12; c++) {
        if (c + 1 < 12) { issue_stage(c + 1, (c + 1) & 1); CP_WAIT1(); }
        else            { CP_WAIT0(); }
        __syncthreads();
        const uint32_t bpu = sb + (c & 1) * STAGE;

#pragma unroll
        for (int kt = 0; kt < 4; kt++) {
            uint32_t aH[MT][4], aL[MT][4];
#pragma unroll
            for (int mt = 0; mt < MT; mt++) {
                const uint32_t soA = swz(wm + mt * 16 + laA, kt * 32 + lbA);
                ldsm4(aH[mt], bpu + AHo + soA);
                if (t3) ldsm4(aL[mt], bpu + ALo + soA);
            }
#pragma unroll
            for (int ntp = 0; ntp < 4; ntp++) {
                const uint32_t soB = swz(wn + ntp * 16 + laB, kt * 32 + lbB);
                uint32_t bH[4], bL[4];
                ldsm4(bH, bpu + BHo + soB);
                if (useBL) ldsm4(bL, bpu + BLo + soB);
#pragma unroll
                for (int mt = 0; mt < MT; mt++) {
                    mma_f16(acc[mt][2 * ntp],     aH[mt], bH[0], bH[1]);
                    mma_f16(acc[mt][2 * ntp + 1], aH[mt], bH[2], bH[3]);
                }
                if (useBL) {
#pragma unroll
                    for (int mt = 0; mt < MT; mt++) {
                        mma_f16(acc[mt][2 * ntp],     aH[mt], bL[0], bL[1]);
                        mma_f16(acc[mt][2 * ntp + 1], aH[mt], bL[2], bL[3]);
                    }
                }
                if (t3) {
#pragma unroll
                    for (int mt = 0; mt < MT; mt++) {
                        mma_f16(acc[mt][2 * ntp],     aL[mt], bH[0], bH[1]);
                        mma_f16(acc[mt][2 * ntp + 1], aL[mt], bH[2], bH[3]);
                    }
                }
            }
        }
        __syncthreads();
    }

    // Epilogue
    const int r = lane >> 2;
#pragma unroll
    for (int mt = 0; mt < MT; mt++) {
        const int mrow = m0 + wm + mt * 16 + r;
#pragma unroll
        for (int nt = 0; nt < 8; nt++) {
            const int nl = wn + nt * 8 + 2 * (lane & 3);
            float d0 = acc[mt][nt][0], d1 = acc[mt][nt][1];
            float d2 = acc[mt][nt][2], d3 = acc[mt][nt][3];
            if (MODE == 0) {
                const int koff = by * 2 + (nl >> 6);
                const int dh = nl & 63;
                const int k3 = koff / 12;
                const int h = koff - 12 * k3;
                const int b = mrow >> 11;
                const int t = mrow & 2047;
                const int bhI = b * NH + h;
                if (k3 == 0) { d0 *= QSCALE; d1 *= QSCALE; d2 *= QSCALE; d3 *= QSCALE; }
                if (k3 == 2) {
                    uint32_t h0 = packh2(d0, d1), h1 = packh2(d2, d3);
                    size_t q0 = ((size_t)bhI * DH + dh) * T_SEQ + t;
                    size_t q1 = ((size_t)bhI * DH + dh + 1) * T_SEQ + t;
                    g_vth[q0] = (uint16_t)h0;      g_vth[q1] = (uint16_t)(h0 >> 16);
                    g_vth[q0 + 8] = (uint16_t)h1;  g_vth[q1 + 8] = (uint16_t)(h1 >> 16);
                } else {
                    uint32_t h0, l0, h1, l1;
                    split2(d0, d1, h0, l0);
                    split2(d2, d3, h1, l1);
                    uint16_t* dsth = (k3 == 0) ? g_qh : g_kh;
                    uint16_t* dstl = (k3 == 0) ? g_ql : g_kl;
                    size_t p0 = ((size_t)bhI * T_SEQ + t) * DH + dh;
                    size_t p1 = ((size_t)bhI * T_SEQ + t + 8) * DH + dh;
                    *reinterpret_cast<uint32_t*>(dsth + p0) = h0;
                    *reinterpret_cast<uint32_t*>(dstl + p0) = l0;
                    *reinterpret_cast<uint32_t*>(dsth + p1) = h1;
                    *reinterpret_cast<uint32_t*>(dstl + p1) = l1;
                }
            } else {
                float2 p0{d0, d1}, p1{d2, d3};
                *reinterpret_cast<float2*>(C + (size_t)mrow * DMODEL + by * 128 + nl) = p0;
                *reinterpret_cast<float2*>(C + (size_t)(mrow + 8) * DMODEL + by * 128 + nl) = p1;
            }
        }
    }
}

// ---------------------------------------------------------------------------
// Flash attention: 128 threads (4 warps), warp tile 32 q-rows x 64 keys.
// QK^T 3-term, PV single-term. Base-2 softmax. cp.async double-buffered KV.
// ldmatrix fragment loads throughout.
// ---------------------------------------------------------------------------
#define ATTN_KV_BUF   24576
#define ATTN_SMEM_BYTES (32768 + 2 * ATTN_KV_BUF)

__global__ void __launch_bounds__(128) attn_mma() {
    extern __shared__ char smem[];
    const uint32_t sb = smem_u32(smem);
    const int QHo = 0, QLo = 16384;
    const int KHo = 0, KLo = 8192, VHo = 16384;     // within KV stage

    const int tid = threadIdx.x;
    const int lane = tid & 31;
    const int wid = tid >> 5;
    const int r = lane >> 2;
    const int bh = blockIdx.y;
    const int t0 = blockIdx.x * 128;
    const int wrow = wid * 32;

    const int laA = lane & 15;
    const int lbA = (lane >> 4) * 16;
    const int laB = (lane >> 4) * 8 + (lane & 7);
    const int lbB = ((lane >> 3) & 1) * 16;

    const uint16_t* kh = g_kh + (size_t)bh * T_SEQ * DH;
    const uint16_t* kl = g_kl + (size_t)bh * T_SEQ * DH;
    const uint16_t* vh = g_vth + (size_t)bh * DH * T_SEQ;

    auto issue_kv = [&](int kt, int buf) {
        const uint32_t base = sb + 32768 + buf * ATTN_KV_BUF;
#pragma unroll
        for (int it = 0; it < 4; it++) {
            const int idx = it * 128 + tid;
            const int row = idx >> 3;
            const int ch = idx & 7;
            const uint32_t so = swz(row, ch * 16);
            CP_ASYNC16(base + KHo + so, kh + (size_t)(kt * 64 + row) * DH + ch * 8);
            CP_ASYNC16(base + KLo + so, kl + (size_t)(kt * 64 + row) * DH + ch * 8);
            CP_ASYNC16(base + VHo + so, vh + (size_t)row * T_SEQ + kt * 64 + ch * 8);
        }
        CP_COMMIT();
    };

    issue_kv(0, 0);

    const uint16_t* qhp = g_qh + ((size_t)bh * T_SEQ + t0) * DH;
    const uint16_t* qlp = g_ql + ((size_t)bh * T_SEQ + t0) * DH;
#pragma unroll
    for (int it = 0; it < 8; it++) {
        const int idx = it * 128 + tid;
        const int row = idx >> 3;
        const int ch = idx & 7;
        const uint32_t so = swz(row, ch * 16);
        *reinterpret_cast<uint4*>(smem + QHo + so) =
            *(reinterpret_cast<const uint4*>(qhp + (size_t)row * DH) + ch);
        *reinterpret_cast<uint4*>(smem + QLo + so) =
            *(reinterpret_cast<const uint4*>(qlp + (size_t)row * DH) + ch);
    }

    float mS[2][2], lS[2][2];
#pragma unroll
    for (int mt = 0; mt < 2; mt++) { mS[mt][0] = mS[mt][1] = -1e30f; lS[mt][0] = lS[mt][1] = 0.0f; }

    float o[2][8][4];
#pragma unroll
    for (int mt = 0; mt < 2; mt++)
#pragma unroll
        for (int nt = 0; nt < 8; nt++)
#pragma unroll
            for (int q = 0; q < 4; q++) o[mt][nt][q] = 0.0f;

    for (int kt64 = 0; kt64 < T_SEQ / 64; kt64++) {
        if (kt64 + 1 < T_SEQ / 64) { issue_kv(kt64 + 1, (kt64 + 1) & 1); CP_WAIT1(); }
        else                       { CP_WAIT0(); }
        __syncthreads();
        const uint32_t kvb = sb + 32768 + (kt64 & 1) * ATTN_KV_BUF;

        // ---- S2 = (Q*8*log2e) K^T, 3-term ----
        float s[2][8][4];
#pragma unroll
        for (int mt = 0; mt < 2; mt++)
#pragma unroll
            for (int nt = 0; nt < 8; nt++)
#pragma unroll
                for (int q = 0; q < 4; q++) s[mt][nt][q] = 0.0f;

#pragma unroll
        for (int kt = 0; kt < 4; kt++) {
            uint32_t qa[2][4], qb[2][4];
#pragma unroll
            for (int mt = 0; mt < 2; mt++) {
                const uint32_t soQ = swz(wrow + mt * 16 + laA, kt * 32 + lbA);
                ldsm4(qa[mt], sb + QHo + soQ);
                ldsm4(qb[mt], sb + QLo + soQ);
            }
#pragma unroll
            for (int ntp = 0; ntp < 4; ntp++) {
                const uint32_t soK = swz(ntp * 16 + laB, kt * 32 + lbB);
                uint32_t kH[4], kL[4];
                ldsm4(kH, kvb + KHo + soK);
                ldsm4(kL, kvb + KLo + soK);
                mma_f16(s[0][2 * ntp],     qa[0], kH[0], kH[1]);
                mma_f16(s[1][2 * ntp],     qa[1], kH[0], kH[1]);
                mma_f16(s[0][2 * ntp + 1], qa[0], kH[2], kH[3]);
                mma_f16(s[1][2 * ntp + 1], qa[1], kH[2], kH[3]);
                mma_f16(s[0][2 * ntp],     qa[0], kL[0], kL[1]);
                mma_f16(s[1][2 * ntp],     qa[1], kL[0], kL[1]);
                mma_f16(s[0][2 * ntp + 1], qa[0], kL[2], kL[3]);
                mma_f16(s[1][2 * ntp + 1], qa[1], kL[2], kL[3]);
                mma_f16(s[0][2 * ntp],     qb[0], kH[0], kH[1]);
                mma_f16(s[1][2 * ntp],     qb[1], kH[0], kH[1]);
                mma_f16(s[0][2 * ntp + 1], qb[0], kH[2], kH[3]);
                mma_f16(s[1][2 * ntp + 1], qb[1], kH[2], kH[3]);
            }
        }

        // ---- online softmax (base-2; registers; quad shfl reduce) ----
        float alpha[2][2];
#pragma unroll
        for (int mt = 0; mt < 2; mt++) {
            float mx0 = -1e30f, mx1 = -1e30f;
#pragma unroll
            for (int nt = 0; nt < 8; nt++) {
                mx0 = fmaxf(mx0, fmaxf(s[mt][nt][0], s[mt][nt][1]));
                mx1 = fmaxf(mx1, fmaxf(s[mt][nt][2], s[mt][nt][3]));
            }
            mx0 = fmaxf(mx0, __shfl_xor_sync(0xffffffffu, mx0, 1));
            mx0 = fmaxf(mx0, __shfl_xor_sync(0xffffffffu, mx0, 2));
            mx1 = fmaxf(mx1, __shfl_xor_sync(0xffffffffu, mx1, 1));
            mx1 = fmaxf(mx1, __shfl_xor_sync(0xffffffffu, mx1, 2));

            const float mn0 = fmaxf(mS[mt][0], mx0);
            const float mn1 = fmaxf(mS[mt][1], mx1);
            alpha[mt][0] = ex2f(mS[mt][0] - mn0);
            alpha[mt][1] = ex2f(mS[mt][1] - mn1);
            mS[mt][0] = mn0; mS[mt][1] = mn1;

            float rs0 = 0.0f, rs1 = 0.0f;
#pragma unroll
            for (int nt = 0; nt < 8; nt++) {
                float p0 = ex2f(s[mt][nt][0] - mn0);
                float p1 = ex2f(s[mt][nt][1] - mn0);
                float p2 = ex2f(s[mt][nt][2] - mn1);
                float p3 = ex2f(s[mt][nt][3] - mn1);
                s[mt][nt][0] = p0; s[mt][nt][1] = p1; s[mt][nt][2] = p2; s[mt][nt][3] = p3;
                rs0 += p0 + p1;
                rs1 += p2 + p3;
            }
            rs0 += __shfl_xor_sync(0xffffffffu, rs0, 1);
            rs0 += __shfl_xor_sync(0xffffffffu, rs0, 2);
            rs1 += __shfl_xor_sync(0xffffffffu, rs1, 1);
            rs1 += __shfl_xor_sync(0xffffffffu, rs1, 2);
            lS[mt][0] = lS[mt][0] * alpha[mt][0] + rs0;
            lS[mt][1] = lS[mt][1] * alpha[mt][1] + rs1;

#pragma unroll
            for (int nt = 0; nt < 8; nt++) {
                o[mt][nt][0] *= alpha[mt][0]; o[mt][nt][1] *= alpha[mt][0];
                o[mt][nt][2] *= alpha[mt][1]; o[mt][nt][3] *= alpha[mt][1];
            }
        }

        // ---- O += P V : single-term (P hi only) ----
#pragma unroll
        for (int kt = 0; kt < 4; kt++) {
            uint32_t ph[2][4];
#pragma unroll
            for (int mt = 0; mt < 2; mt++) {
                ph[mt][0] = packh2(s[mt][2 * kt][0],     s[mt][2 * kt][1]);
                ph[mt][1] = packh2(s[mt][2 * kt][2],     s[mt][2 * kt][3]);
                ph[mt][2] = packh2(s[mt][2 * kt + 1][0], s[mt][2 * kt + 1][1]);
                ph[mt][3] = packh2(s[mt][2 * kt + 1][2], s[mt][2 * kt + 1][3]);
            }
#pragma unroll
            for (int ntp = 0; ntp < 4; ntp++) {
                const uint32_t soV = swz(ntp * 16 + laB, kt * 32 + lbB);
                uint32_t vv[4];
                ldsm4(vv, kvb + VHo + soV);
                mma_f16(o[0][2 * ntp],     ph[0], vv[0], vv[1]);
                mma_f16(o[1][2 * ntp],     ph[1], vv[0], vv[1]);
                mma_f16(o[0][2 * ntp + 1], ph[0], vv[2], vv[3]);
                mma_f16(o[1][2 * ntp + 1], ph[1], vv[2], vv[3]);
            }
        }
        __syncthreads();
    }

    // Writeback -> g_oh only
    const int b = bh / NH;
    const int h = bh - b * NH;
#pragma unroll
    for (int mt = 0; mt < 2; mt++) {
        const float li0 = 1.0f / lS[mt][0];
        const float li1 = 1.0f / lS[mt][1];
        const int t_r = t0 + wrow + mt * 16 + r;
#pragma unroll
        for (int nt = 0; nt < 8; nt++) {
            const int col = h * DH + nt * 8 + 2 * (lane & 3);
            uint32_t h0 = packh2(o[mt][nt][0] * li0, o[mt][nt][1] * li0);
            uint32_t h1 = packh2(o[mt][nt][2] * li1, o[mt][nt][3] * li1);
            size_t p0 = ((size_t)b * T_SEQ + t_r) * DMODEL + col;
            size_t p1 = ((size_t)b * T_SEQ + t_r + 8) * DMODEL + col;
            *reinterpret_cast<uint32_t*>(g_oh + p0) = h0;
            *reinterpret_cast<uint32_t*>(g_oh + p1) = h1;
        }
    }
}

// ---------------------------------------------------------------------------
extern "C" void kernel_launch(void* const* d_in, const int* in_sizes, int n_in,
                              void* d_out, int out_size) {
    const float* x     = (const float*)d_in[0];   // [4, 2048, 768]
    const float* w_qkv = (const float*)d_in[1];   // [2304, 768]
    const float* w_out = (const float*)d_in[2];   // [768, 768]
    float* out = (float*)d_out;                   // [4, 2048, 768]

    constexpr int SMEM0 = 2 * (2 * 256 * 128 + 32768);   // 196608
    constexpr int SMEM1 = 2 * (2 * 128 * 128 + 32768);   // 131072

    cudaFuncSetAttribute((const void*)gemm_mma<0, 256, 256>,
                         cudaFuncAttributeMaxDynamicSharedMemorySize, SMEM0);
    cudaFuncSetAttribute((const void*)gemm_mma<1, 128, 256>,
                         cudaFuncAttributeMaxDynamicSharedMemorySize, SMEM1);
    cudaFuncSetAttribute((const void*)attn_mma,
                         cudaFuncAttributeMaxDynamicSharedMemorySize, ATTN_SMEM_BYTES);

    split_all<<<1024, 256>>>(x, w_qkv, w_out);
    gemm_mma<0, 256, 256><<<dim3(32, 18), 256, SMEM0>>>(nullptr);
    attn_mma<<<dim3(16, 48), 128, ATTN_SMEM_BYTES>>>();
    gemm_mma<1, 128, 256><<<dim3(64, 6), 256, SMEM1>>>(out);
}